// round 12
// baseline (speedup 1.0000x reference)
#include <cuda_runtime.h>
#include <cuda_bf16.h>
#include <cstdint>

// ===========================================================================
// LEFTNet layer. Edge GEMMs: mma.sync bf16 3-term split, pass-INNER K=32
// chunks (each operand loaded once), M=128 tiles, 512 threads.
// Kernel A: t1 = silu(wgt@iw1+ib1) -> bf16 hi/lo planes (wgt converted
//           in-smem, in-place). Kernel B: w2 = t1@iw2+ib2, rbfh = rbf@rw+rb
//           (tensor cores, two N-halves), m = w2*rbfh*xh[src], scatter RED.
// Node GEMMs on FFMA2.
// ===========================================================================

#define NN_MAX 50000
#define NE_MAX 500000

__device__ float g_h1[(size_t)NN_MAX * 128];
__device__ float g_xh[(size_t)NN_MAX * 384];
__device__ __align__(16) __nv_bfloat16 g_t1hi[(size_t)NE_MAX * 384];
__device__ __align__(16) __nv_bfloat16 g_t1lo[(size_t)NE_MAX * 384];
__device__ __align__(16) __nv_bfloat16 g_b1hi[384 * 448];
__device__ __align__(16) __nv_bfloat16 g_b1lo[384 * 448];
__device__ __align__(16) __nv_bfloat16 g_b2hi[384 * 384];
__device__ __align__(16) __nv_bfloat16 g_b2lo[384 * 384];
__device__ __align__(16) __nv_bfloat16 g_rwhi[384 * 64];
__device__ __align__(16) __nv_bfloat16 g_rwlo[384 * 64];

// ---------------------------------------------------------------------------
// helpers
// ---------------------------------------------------------------------------
__device__ __forceinline__ uint32_t smem_u32(const void* p) {
    uint32_t a;
    asm("{ .reg .u64 t; cvta.to.shared.u64 t, %1; cvt.u32.u64 %0, t; }"
        : "=r"(a) : "l"(p));
    return a;
}
__device__ __forceinline__ void cp16(uint32_t s, const void* g, uint32_t nbytes) {
    asm volatile("cp.async.cg.shared.global [%0], [%1], 16, %2;"
                 :: "r"(s), "l"(g), "r"(nbytes) : "memory");
}
__device__ __forceinline__ void cp_commit() { asm volatile("cp.async.commit_group;" ::: "memory"); }
__device__ __forceinline__ void cp_wait0()  { asm volatile("cp.async.wait_group 0;" ::: "memory"); }

#define SWZ64(o) ((o) ^ (((o) >> 3) & 0x30))

__device__ __forceinline__ void ldm_x4(uint32_t& r0, uint32_t& r1, uint32_t& r2, uint32_t& r3,
                                       uint32_t addr) {
    asm volatile("ldmatrix.sync.aligned.m8n8.x4.shared.b16 {%0, %1, %2, %3}, [%4];"
                 : "=r"(r0), "=r"(r1), "=r"(r2), "=r"(r3) : "r"(addr));
}
__device__ __forceinline__ void mma_bf16(float* c, const uint32_t* a, const uint32_t* b) {
    asm volatile("mma.sync.aligned.m16n8k16.row.col.f32.bf16.bf16.f32 "
                 "{%0, %1, %2, %3}, {%4, %5, %6, %7}, {%8, %9}, {%0, %1, %2, %3};"
                 : "+f"(c[0]), "+f"(c[1]), "+f"(c[2]), "+f"(c[3])
                 : "r"(a[0]), "r"(a[1]), "r"(a[2]), "r"(a[3]), "r"(b[0]), "r"(b[1]));
}
__device__ __forceinline__ void red_add_v4(float* p, float4 v) {
    asm volatile("red.global.add.v4.f32 [%0], {%1, %2, %3, %4};"
                 :: "l"(p), "f"(v.x), "f"(v.y), "f"(v.z), "f"(v.w) : "memory");
}
__device__ __forceinline__ float silu_f(float v) {
    return v * (1.0f / (1.0f + __expf(-v)));
}
__device__ __forceinline__ void split_bf16(float v, __nv_bfloat16& h, __nv_bfloat16& l) {
    h = __float2bfloat16(v);
    l = __float2bfloat16(v - __bfloat162float(h));
}

// mma over one K=32 chunk (2 k16 steps). Warp tile 32x96.
// acc[2][12][4], A rows 64B SW64, B rows 64B SW64.
__device__ __forceinline__ void mma_chunk32(float (*acc)[12][4],
                                            uint32_t Ab, uint32_t Bb,
                                            int wm, int wn,
                                            int a_r, int a_c, int b_r, int b_c)
{
#pragma unroll
    for (int ks = 0; ks < 2; ks++) {
        uint32_t af[2][4];
#pragma unroll
        for (int mt = 0; mt < 2; mt++) {
            int r = wm + mt * 16 + a_r;
            ldm_x4(af[mt][0], af[mt][1], af[mt][2], af[mt][3],
                   Ab + SWZ64(r * 64 + (ks * 2 + a_c) * 16));
        }
#pragma unroll
        for (int np = 0; np < 6; np++) {
            int r = wn + np * 16 + b_r;
            uint32_t b0, b1, b2, b3;
            ldm_x4(b0, b1, b2, b3, Bb + SWZ64(r * 64 + (ks * 2 + b_c) * 16));
            uint32_t bfa[2] = {b0, b1}, bfb[2] = {b2, b3};
#pragma unroll
            for (int mt = 0; mt < 2; mt++) {
                mma_bf16(acc[mt][np * 2 + 0], af[mt], bfa);
                mma_bf16(acc[mt][np * 2 + 1], af[mt], bfb);
            }
        }
    }
}

// ---------------------------------------------------------------------------
// Kernel A: t1 = silu(wgt @ iw1 + ib1) -> bf16 hi/lo planes.
// 13 K=32 chunks; stage = [A fp32 128x144B -> hi/lo 8K+8K][Bhi 24K][Blo 24K]
// ---------------------------------------------------------------------------
#define KA_BHI   18432
#define KA_BLO   (18432 + 24576)
#define KA_STAGE 67584
#define KA_SMEM  (2 * KA_STAGE)

__global__ __launch_bounds__(512)
void gemm4_kernel(const float* __restrict__ wgt,
                  const __nv_bfloat16* __restrict__ B1hi,
                  const __nv_bfloat16* __restrict__ B1lo,
                  int E, const float* __restrict__ ib1,
                  __nv_bfloat16* __restrict__ t1hi, __nv_bfloat16* __restrict__ t1lo)
{
    extern __shared__ char dsm[];
    const uint32_t S0 = smem_u32(dsm);
    const int tid  = threadIdx.x;
    const int wid  = tid >> 5;
    const int lane = tid & 31;
    const int row0 = blockIdx.x * 128;

    const int wm  = (wid >> 2) * 32;
    const int wn  = (wid & 3) * 96;
    const int gq  = lane >> 2;
    const int tig = lane & 3;
    const int a_r = (lane & 7) + ((lane & 8) ? 8 : 0);
    const int a_c = lane >> 4;
    const int b_r = (lane & 7) + ((lane & 16) ? 8 : 0);
    const int b_c = (lane >> 3) & 1;

    float acc[2][12][4];
#pragma unroll
    for (int i = 0; i < 2; i++)
#pragma unroll
        for (int j = 0; j < 12; j++)
#pragma unroll
            for (int k = 0; k < 4; k++) acc[i][j][k] = 0.0f;

    auto load_chunk = [&](int c) {
        const uint32_t S = S0 + (c & 1) * KA_STAGE;
        const int k0 = c * 32;
        // A fp32: 128 rows x 8 x 16B (row stride 144B to dodge bank conflicts)
#pragma unroll
        for (int i = 0; i < 2; i++) {
            int id = tid + i * 512;
            int r = id >> 3, u = id & 7;
            int gr = row0 + r; if (gr >= E) gr = E - 1;
            cp16(S + r * 144 + u * 16, wgt + (size_t)gr * 416 + k0 + u * 4, 16u);
        }
        // B planes: 384 rows x 4 x 16B each (flat over 1536 elements)
#pragma unroll
        for (int i = 0; i < 3; i++) {
            int id = tid + i * 512;
            int r = id >> 2, u = id & 3;
            cp16(S + KA_BHI + SWZ64(r * 64 + u * 16),
                 B1hi + (size_t)r * 416 + k0 + u * 8, 16u);
        }
#pragma unroll
        for (int i = 0; i < 3; i++) {
            int id = tid + i * 512;
            int r = id >> 2, u = id & 3;
            cp16(S + KA_BLO + SWZ64(r * 64 + u * 16),
                 B1lo + (size_t)r * 416 + k0 + u * 8, 16u);
        }
        cp_commit();
    };

    load_chunk(0);

    for (int c = 0; c < 13; c++) {
        const uint32_t S = S0 + (c & 1) * KA_STAGE;
        char* Sc = dsm + (c & 1) * KA_STAGE;

        cp_wait0();
        __syncthreads();                 // load c visible; mma c-1 done everywhere
        if (c + 1 < 13) load_chunk(c + 1);

        // in-place convert: thread -> (row = tid>>2, grp = tid&3), 8 floats
        const int cr = tid >> 2, cg = tid & 3;
        float4 v0 = *(const float4*)(Sc + cr * 144 + cg * 32);
        float4 v1 = *(const float4*)(Sc + cr * 144 + cg * 32 + 16);
        __syncthreads();                 // all reads done before overwrite
        {
            float a[8] = {v0.x, v0.y, v0.z, v0.w, v1.x, v1.y, v1.z, v1.w};
            uint32_t H[4], L[4];
#pragma unroll
            for (int q = 0; q < 4; q++) {
                __nv_bfloat16 h0, l0, h1, l1;
                split_bf16(a[2 * q + 0], h0, l0);
                split_bf16(a[2 * q + 1], h1, l1);
                H[q] = (uint32_t)__bfloat16_as_ushort(h0) |
                       ((uint32_t)__bfloat16_as_ushort(h1) << 16);
                L[q] = (uint32_t)__bfloat16_as_ushort(l0) |
                       ((uint32_t)__bfloat16_as_ushort(l1) << 16);
            }
            uint32_t off = SWZ64(cr * 64 + cg * 16);
            *(uint4*)(Sc + off)        = make_uint4(H[0], H[1], H[2], H[3]);
            *(uint4*)(Sc + 8192 + off) = make_uint4(L[0], L[1], L[2], L[3]);
        }
        __syncthreads();                 // planes visible before ldmatrix

        mma_chunk32(acc, S + 0,    S + KA_BHI, wm, wn, a_r, a_c, b_r, b_c); // hi*hi
        mma_chunk32(acc, S + 8192, S + KA_BHI, wm, wn, a_r, a_c, b_r, b_c); // lo*hi
        mma_chunk32(acc, S + 0,    S + KA_BLO, wm, wn, a_r, a_c, b_r, b_c); // hi*lo
    }

    // epilogue: silu -> bf16 hi/lo planes
#pragma unroll
    for (int mt = 0; mt < 2; mt++)
#pragma unroll
        for (int half = 0; half < 2; half++) {
            const int e = row0 + wm + mt * 16 + gq + half * 8;
            if (e >= E) continue;
#pragma unroll
            for (int nt = 0; nt < 12; nt++) {
                const int col = wn + nt * 8 + tig * 2;
                float s0 = silu_f(acc[mt][nt][half * 2 + 0] + ib1[col]);
                float s1 = silu_f(acc[mt][nt][half * 2 + 1] + ib1[col + 1]);
                __nv_bfloat16 h0, l0, h1, l1;
                split_bf16(s0, h0, l0);
                split_bf16(s1, h1, l1);
                *(uint32_t*)&t1hi[(size_t)e * 384 + col] =
                    (uint32_t)__bfloat16_as_ushort(h0) |
                    ((uint32_t)__bfloat16_as_ushort(h1) << 16);
                *(uint32_t*)&t1lo[(size_t)e * 384 + col] =
                    (uint32_t)__bfloat16_as_ushort(l0) |
                    ((uint32_t)__bfloat16_as_ushort(l1) << 16);
            }
        }
}

// ---------------------------------------------------------------------------
// Kernel B: w2 = t1@iw2+ib2; rbfh = rbf@rw+rb (TC, two N-halves);
// m = w2*rbfh*xh[src]; scatter RED into dx/dvec.
// stages: [A hi 8K | A lo 8K | Bhi 24K | Blo 24K] x2 = 128K
// m_st: 128 x 388 fp32 = 198656 (aliases stages after mainloop)
// rbf region: 18432 @198656 ; rw half-plane: 12288 @217088
// ---------------------------------------------------------------------------
#define KB_BHI   16384
#define KB_BLO   (16384 + 24576)
#define KB_STAGE 65536
#define KB_RA    198656
#define KB_RB    (198656 + 18432)
#define KB_SMEM  (198656 + 18432 + 12288)

__global__ __launch_bounds__(512)
void gemm5_kernel(const __nv_bfloat16* __restrict__ t1hi,
                  const __nv_bfloat16* __restrict__ t1lo,
                  const __nv_bfloat16* __restrict__ B2hi,
                  const __nv_bfloat16* __restrict__ B2lo,
                  const __nv_bfloat16* __restrict__ RWhi,
                  const __nv_bfloat16* __restrict__ RWlo,
                  const float* __restrict__ rbf,
                  const float* __restrict__ ib2, const float* __restrict__ rb,
                  const float* __restrict__ xh,
                  const int* __restrict__ ei, int E,
                  const float* __restrict__ vec, const float* __restrict__ ev,
                  float* __restrict__ dx, float* __restrict__ dvec)
{
    extern __shared__ char dsm[];
    const uint32_t S0 = smem_u32(dsm);
    float* m_st = (float*)dsm;                    // stride 388
    const int tid  = threadIdx.x;
    const int wid  = tid >> 5;
    const int lane = tid & 31;
    const int row0 = blockIdx.x * 128;

    const int wm  = (wid >> 2) * 32;
    const int wn  = (wid & 3) * 96;
    const int gq  = lane >> 2;
    const int tig = lane & 3;
    const int a_r = (lane & 7) + ((lane & 8) ? 8 : 0);
    const int a_c = lane >> 4;
    const int b_r = (lane & 7) + ((lane & 16) ? 8 : 0);
    const int b_c = (lane >> 3) & 1;

    float acc[2][12][4];
#pragma unroll
    for (int i = 0; i < 2; i++)
#pragma unroll
        for (int j = 0; j < 12; j++)
#pragma unroll
            for (int k = 0; k < 4; k++) acc[i][j][k] = 0.0f;

    auto load_chunk = [&](int c) {
        const uint32_t S = S0 + (c & 1) * KB_STAGE;
        const int k0 = c * 32;
        // A planes: each thread loads one 16B unit of BOTH planes at the
        // same (r,u). (R11 bug: flat index sent the lo plane to r in
        // [128,256) — wrong rows AND left [8K,16K) uninitialized.)
        {
            int r = tid >> 2, u = tid & 3;
            int gr = row0 + r; if (gr >= E) gr = E - 1;
            uint32_t off = SWZ64(r * 64 + u * 16);
            size_t gidx = (size_t)gr * 384 + k0 + u * 8;
            cp16(S + off,        t1hi + gidx, 16u);
            cp16(S + 8192 + off, t1lo + gidx, 16u);
        }
#pragma unroll
        for (int i = 0; i < 3; i++) {
            int id = tid + i * 512;
            int r = id >> 2, u = id & 3;
            cp16(S + KB_BHI + SWZ64(r * 64 + u * 16),
                 B2hi + (size_t)r * 384 + k0 + u * 8, 16u);
        }
#pragma unroll
        for (int i = 0; i < 3; i++) {
            int id = tid + i * 512;
            int r = id >> 2, u = id & 3;
            cp16(S + KB_BLO + SWZ64(r * 64 + u * 16),
                 B2lo + (size_t)r * 384 + k0 + u * 8, 16u);
        }
        cp_commit();
    };

    load_chunk(0);
    for (int c = 0; c < 12; c++) {
        const uint32_t S = S0 + (c & 1) * KB_STAGE;
        cp_wait0();
        __syncthreads();
        if (c + 1 < 12) load_chunk(c + 1);
        mma_chunk32(acc, S + 0,    S + KB_BHI, wm, wn, a_r, a_c, b_r, b_c);
        mma_chunk32(acc, S + 8192, S + KB_BHI, wm, wn, a_r, a_c, b_r, b_c);
        mma_chunk32(acc, S + 0,    S + KB_BLO, wm, wn, a_r, a_c, b_r, b_c);
    }
    __syncthreads();                               // mainloop smem reads done

    // stage w2 + ib2 into m_st
#pragma unroll
    for (int mt = 0; mt < 2; mt++)
#pragma unroll
        for (int half = 0; half < 2; half++) {
            const int er = wm + mt * 16 + gq + half * 8;
#pragma unroll
            for (int nt = 0; nt < 12; nt++) {
                const int col = wn + nt * 8 + tig * 2;
                float2 o;
                o.x = acc[mt][nt][half * 2 + 0] + ib2[col];
                o.y = acc[mt][nt][half * 2 + 1] + ib2[col + 1];
                *(float2*)&m_st[er * 388 + col] = o;
            }
        }

    // ---- rbfh: rbf @ rw^T via tensor cores ----
#pragma unroll
    for (int i = 0; i < 2; i++)
#pragma unroll
        for (int j = 0; j < 12; j++)
#pragma unroll
            for (int k = 0; k < 4; k++) acc[i][j][k] = 0.0f;

    // load rbf fp32 (128 x 32, stride 144B)
#pragma unroll
    for (int i = 0; i < 2; i++) {
        int id = tid + i * 512;
        int r = id >> 3, u = id & 7;
        int gr = row0 + r; if (gr >= E) gr = E - 1;
        cp16(S0 + KB_RA + r * 144 + u * 16, rbf + (size_t)gr * 32 + u * 4, 16u);
    }
    cp_commit(); cp_wait0(); __syncthreads();
    {
        const int cr = tid >> 2, cg = tid & 3;
        float4 v0 = *(const float4*)(dsm + KB_RA + cr * 144 + cg * 32);
        float4 v1 = *(const float4*)(dsm + KB_RA + cr * 144 + cg * 32 + 16);
        __syncthreads();
        float a[8] = {v0.x, v0.y, v0.z, v0.w, v1.x, v1.y, v1.z, v1.w};
        uint32_t H[4], L[4];
#pragma unroll
        for (int q = 0; q < 4; q++) {
            __nv_bfloat16 h0, l0, h1, l1;
            split_bf16(a[2 * q + 0], h0, l0);
            split_bf16(a[2 * q + 1], h1, l1);
            H[q] = (uint32_t)__bfloat16_as_ushort(h0) |
                   ((uint32_t)__bfloat16_as_ushort(h1) << 16);
            L[q] = (uint32_t)__bfloat16_as_ushort(l0) |
                   ((uint32_t)__bfloat16_as_ushort(l1) << 16);
        }
        uint32_t off = SWZ64(cr * 64 + cg * 16);
        *(uint4*)(dsm + KB_RA + off)        = make_uint4(H[0], H[1], H[2], H[3]);
        *(uint4*)(dsm + KB_RA + 8192 + off) = make_uint4(L[0], L[1], L[2], L[3]);
        __syncthreads();
    }

    // two N-halves of rw (192 rows each)
    for (int h = 0; h < 2; h++) {
        const bool mine = (((wid & 3) < 2) == (h == 0));
        const int wnl = wn - h * 192;              // local warp n for mine warps
        // load rw hi half: 192 rows x 4 units = 768 cp16
        {
            int id = tid;
            if (id < 768) {
                int r = id >> 2, u = id & 3;
                cp16(S0 + KB_RB + SWZ64(r * 64 + u * 16),
                     RWhi + (size_t)(h * 192 + r) * 32 + u * 8, 16u);
            }
            int id2 = tid + 512;
            if (id2 < 768) {
                int r = id2 >> 2, u = id2 & 3;
                cp16(S0 + KB_RB + SWZ64(r * 64 + u * 16),
                     RWhi + (size_t)(h * 192 + r) * 32 + u * 8, 16u);
            }
        }
        cp_commit(); cp_wait0(); __syncthreads();
        if (mine) {
            mma_chunk32(acc, S0 + KB_RA,        S0 + KB_RB, wm, wnl, a_r, a_c, b_r, b_c);
            mma_chunk32(acc, S0 + KB_RA + 8192, S0 + KB_RB, wm, wnl, a_r, a_c, b_r, b_c);
        }
        __syncthreads();
        {
            int id = tid;
            if (id < 768) {
                int r = id >> 2, u = id & 3;
                cp16(S0 + KB_RB + SWZ64(r * 64 + u * 16),
                     RWlo + (size_t)(h * 192 + r) * 32 + u * 8, 16u);
            }
            int id2 = tid + 512;
            if (id2 < 768) {
                int r = id2 >> 2, u = id2 & 3;
                cp16(S0 + KB_RB + SWZ64(r * 64 + u * 16),
                     RWlo + (size_t)(h * 192 + r) * 32 + u * 8, 16u);
            }
        }
        cp_commit(); cp_wait0(); __syncthreads();
        if (mine)
            mma_chunk32(acc, S0 + KB_RA, S0 + KB_RB, wm, wnl, a_r, a_c, b_r, b_c);
        __syncthreads();
    }

    // multiply own cells: m_st *= (rbfh + rb)
#pragma unroll
    for (int mt = 0; mt < 2; mt++)
#pragma unroll
        for (int half = 0; half < 2; half++) {
            const int er = wm + mt * 16 + gq + half * 8;
#pragma unroll
            for (int nt = 0; nt < 12; nt++) {
                const int col = wn + nt * 8 + tig * 2;
                float2 o = *(float2*)&m_st[er * 388 + col];
                o.x *= acc[mt][nt][half * 2 + 0] + rb[col];
                o.y *= acc[mt][nt][half * 2 + 1] + rb[col + 1];
                *(float2*)&m_st[er * 388 + col] = o;
            }
        }
    __syncthreads();

    // ---- scatter: 16 warps x 8 edges ----
    const float is3 = 0.57735026918962576f;       // 1/sqrt(3)
    const float ish = 0.08838834764831845f;       // 1/sqrt(128)
#pragma unroll
    for (int i = 0; i < 8; i++) {
        const int er = wid * 8 + i;
        const int e  = row0 + er;
        if (e >= E) continue;
        const int s = ei[e];
        const int d = ei[E + e];

        const float* st = m_st + er * 388;
        float4 a0 = *(const float4*)&st[lane * 4];
        float4 a1 = *(const float4*)&st[128 + lane * 4];
        float4 a2 = *(const float4*)&st[256 + lane * 4];

        const float* xr = xh + (size_t)s * 384;
        float4 x0 = *(const float4*)&xr[lane * 4];
        float4 x1 = *(const float4*)&xr[128 + lane * 4];
        float4 x2 = *(const float4*)&xr[256 + lane * 4];

        float4 xm, h2, h3;
        xm.x = a0.x * x0.x;  xm.y = a0.y * x0.y;
        xm.z = a0.z * x0.z;  xm.w = a0.w * x0.w;
        h2.x = a1.x * x1.x * is3;  h2.y = a1.y * x1.y * is3;
        h2.z = a1.z * x1.z * is3;  h2.w = a1.w * x1.w * is3;
        h3.x = a2.x * x2.x;  h3.y = a2.y * x2.y;
        h3.z = a2.z * x2.z;  h3.w = a2.w * x2.w;

        red_add_v4(dx + (size_t)d * 128 + lane * 4, xm);

        float evd[3];
        evd[0] = __ldg(&ev[(size_t)e * 3 + 0]);
        evd[1] = __ldg(&ev[(size_t)e * 3 + 1]);
        evd[2] = __ldg(&ev[(size_t)e * 3 + 2]);
        const float4* v4 = (const float4*)(vec + (size_t)s * 384);
#pragma unroll
        for (int t = 0; t < 3; t++) {
            float4 v = v4[t * 32 + lane];
            float4 o;
            o.x = (v.x * h2.x + h3.x * evd[t]) * ish;
            o.y = (v.y * h2.y + h3.y * evd[t]) * ish;
            o.z = (v.z * h2.z + h3.z * evd[t]) * ish;
            o.w = (v.w * h2.w + h3.w * evd[t]) * ish;
            red_add_v4(dvec + ((size_t)d * 3 + t) * 128 + lane * 4, o);
        }
    }
}

// ---------------------------------------------------------------------------
// Transpose+split weights: src [K,N] fp32 -> hi/lo [N,KP] bf16
// ---------------------------------------------------------------------------
__global__ void splitT(const float* __restrict__ src,
                       __nv_bfloat16* __restrict__ hi,
                       __nv_bfloat16* __restrict__ lo,
                       int K, int N, int KP)
{
    int t = blockIdx.x * blockDim.x + threadIdx.x;
    if (t >= N * KP) return;
    int n = t / KP, k = t - n * KP;
    float v = (k < K) ? src[(size_t)k * N + n] : 0.0f;
    __nv_bfloat16 h, l;
    h = __float2bfloat16(v);
    l = __float2bfloat16(v - __bfloat162float(h));
    hi[t] = h;
    lo[t] = l;
}

// ---------------------------------------------------------------------------
// FFMA2 SGEMM for the node GEMMs
// ---------------------------------------------------------------------------
#define BM 128
#define BN 128
#define BK 16

__device__ __forceinline__ unsigned long long pack2(float lo, float hi) {
    unsigned long long r;
    asm("mov.b64 %0, {%1, %2};" : "=l"(r) : "f"(lo), "f"(hi));
    return r;
}
__device__ __forceinline__ void unpack2(unsigned long long v, float& lo, float& hi) {
    asm("mov.b64 {%0, %1}, %2;" : "=f"(lo), "=f"(hi) : "l"(v));
}
__device__ __forceinline__ void ffma2(unsigned long long& d,
                                      unsigned long long a, unsigned long long b) {
    asm("fma.rn.f32x2 %0, %1, %2, %0;" : "+l"(d) : "l"(a), "l"(b));
}

template<bool SILU>
__global__ __launch_bounds__(256, 2)
void sgemm_bias_act(const float* __restrict__ A, const float* __restrict__ B,
                    const float* __restrict__ bias, float* __restrict__ C,
                    int M, int N, int K)
{
    __shared__ float As[BK][BM + 4];
    __shared__ float Bs[BK][BN];

    const int tid  = threadIdx.x;
    const int tx   = tid & 15;
    const int ty   = tid >> 4;
    const int row0 = blockIdx.y * BM;
    const int col0 = blockIdx.x * BN;

    unsigned long long acc2[8][4];
#pragma unroll
    for (int i = 0; i < 8; i++)
#pragma unroll
        for (int j = 0; j < 4; j++) acc2[i][j] = 0ull;

    const int a_row = tid >> 2;
    const int a_seg = tid & 3;
    const int b_kk  = tid >> 5;
    const int b_c4  = (tid & 31) << 2;

    for (int k0 = 0; k0 < K; k0 += BK) {
#pragma unroll
        for (int it = 0; it < 2; it++) {
            int r  = a_row + it * 64;
            int gr = row0 + r;
            float4 v = make_float4(0.f, 0.f, 0.f, 0.f);
            if (gr < M)
                v = *(const float4*)&A[(size_t)gr * K + k0 + a_seg * 4];
            As[a_seg * 4 + 0][r] = v.x;
            As[a_seg * 4 + 1][r] = v.y;
            As[a_seg * 4 + 2][r] = v.z;
            As[a_seg * 4 + 3][r] = v.w;
        }
#pragma unroll
        for (int it = 0; it < 2; it++) {
            int kk = b_kk + it * 8;
            *(float4*)&Bs[kk][b_c4] =
                *(const float4*)&B[(size_t)(k0 + kk) * N + col0 + b_c4];
        }
        __syncthreads();

#pragma unroll
        for (int kk = 0; kk < BK; kk++) {
            float4 a0 = *(const float4*)&As[kk][ty * 4];
            float4 a1 = *(const float4*)&As[kk][64 + ty * 4];
            float4 b0 = *(const float4*)&Bs[kk][tx * 4];
            float4 b1 = *(const float4*)&Bs[kk][64 + tx * 4];
            unsigned long long bp[4] = {
                pack2(b0.x, b0.y), pack2(b0.z, b0.w),
                pack2(b1.x, b1.y), pack2(b1.z, b1.w)
            };
            float av[8] = {a0.x, a0.y, a0.z, a0.w, a1.x, a1.y, a1.z, a1.w};
#pragma unroll
            for (int i = 0; i < 8; i++) {
                unsigned long long ap = pack2(av[i], av[i]);
#pragma unroll
                for (int jp = 0; jp < 4; jp++)
                    ffma2(acc2[i][jp], ap, bp[jp]);
            }
        }
        __syncthreads();
    }

#pragma unroll
    for (int i = 0; i < 8; i++) {
        int r  = (i < 4) ? (ty * 4 + i) : (64 + ty * 4 + (i - 4));
        int gr = row0 + r;
        if (gr >= M) continue;
#pragma unroll
        for (int jg = 0; jg < 2; jg++) {
            int c  = (jg == 0) ? (tx * 4) : (64 + tx * 4);
            int gc = col0 + c;
            float4 bi = *(const float4*)&bias[gc];
            float4 o;
            unpack2(acc2[i][jg * 2 + 0], o.x, o.y);
            unpack2(acc2[i][jg * 2 + 1], o.z, o.w);
            o.x += bi.x; o.y += bi.y; o.z += bi.z; o.w += bi.w;
            if (SILU) {
                o.x = silu_f(o.x); o.y = silu_f(o.y);
                o.z = silu_f(o.z); o.w = silu_f(o.w);
            }
            *(float4*)&C[(size_t)gr * N + gc] = o;
        }
    }
}

// ---------------------------------------------------------------------------
// Launch
// ---------------------------------------------------------------------------
extern "C" void kernel_launch(void* const* d_in, const int* in_sizes, int n_in,
                              void* d_out, int out_size)
{
    const float* x    = (const float*)d_in[0];
    const float* vec  = (const float*)d_in[1];
    const int*   ei   = (const int*)  d_in[2];
    const float* rbf  = (const float*)d_in[3];
    const float* wgt  = (const float*)d_in[4];
    const float* ev   = (const float*)d_in[5];
    const float* xw1  = (const float*)d_in[6];
    const float* xb1  = (const float*)d_in[7];
    const float* xw2  = (const float*)d_in[8];
    const float* xb2  = (const float*)d_in[9];
    const float* rw   = (const float*)d_in[10];
    const float* rb   = (const float*)d_in[11];
    const float* iw1  = (const float*)d_in[12];
    const float* ib1  = (const float*)d_in[13];
    const float* iw2  = (const float*)d_in[14];
    const float* ib2  = (const float*)d_in[15];

    const int nn = in_sizes[0] / 128;
    const int ne = in_sizes[2] / 2;

    float* out  = (float*)d_out;
    float* dx   = out;
    float* dvec = out + (size_t)nn * 128;

    float *p_h1, *p_xh;
    __nv_bfloat16 *p_t1hi, *p_t1lo, *p_b1hi, *p_b1lo, *p_b2hi, *p_b2lo, *p_rwhi, *p_rwlo;
    cudaGetSymbolAddress((void**)&p_h1,  g_h1);
    cudaGetSymbolAddress((void**)&p_xh,  g_xh);
    cudaGetSymbolAddress((void**)&p_t1hi, g_t1hi);
    cudaGetSymbolAddress((void**)&p_t1lo, g_t1lo);
    cudaGetSymbolAddress((void**)&p_b1hi, g_b1hi);
    cudaGetSymbolAddress((void**)&p_b1lo, g_b1lo);
    cudaGetSymbolAddress((void**)&p_b2hi, g_b2hi);
    cudaGetSymbolAddress((void**)&p_b2lo, g_b2lo);
    cudaGetSymbolAddress((void**)&p_rwhi, g_rwhi);
    cudaGetSymbolAddress((void**)&p_rwlo, g_rwlo);

    cudaFuncSetAttribute(gemm4_kernel,
                         cudaFuncAttributeMaxDynamicSharedMemorySize, KA_SMEM);
    cudaFuncSetAttribute(gemm5_kernel,
                         cudaFuncAttributeMaxDynamicSharedMemorySize, KB_SMEM);

    cudaMemsetAsync(d_out, 0, (size_t)out_size * sizeof(float));

    dim3 blk(256);

    // weight conversions (tiny). KP == K everywhere (no padding).
    splitT<<<(384 * 416 + 255) / 256, blk>>>(iw1, p_b1hi, p_b1lo, 416, 384, 416);
    splitT<<<(384 * 384 + 255) / 256, blk>>>(iw2, p_b2hi, p_b2lo, 384, 384, 384);
    splitT<<<(384 * 32  + 255) / 256, blk>>>(rw,  p_rwhi, p_rwlo, 32,  384, 32);

    // node projection (FFMA2): xh = silu(x@xw1+xb1)@xw2+xb2
    sgemm_bias_act<true ><<<dim3(1, (nn + BM - 1) / BM), blk>>>(x,    xw1, xb1, p_h1, nn, 128, 128);
    sgemm_bias_act<false><<<dim3(3, (nn + BM - 1) / BM), blk>>>(p_h1, xw2, xb2, p_xh, nn, 384, 128);

    const int mtiles = (ne + 127) / 128;
    gemm4_kernel<<<mtiles, 512, KA_SMEM>>>(wgt, p_b1hi, p_b1lo, ne, ib1, p_t1hi, p_t1lo);
    gemm5_kernel<<<mtiles, 512, KB_SMEM>>>(p_t1hi, p_t1lo, p_b2hi, p_b2lo,
                                           p_rwhi, p_rwlo, rbf, ib2, rb,
                                           p_xh, ei, ne, vec, ev, dx, dvec);
}

// round 13
// speedup vs baseline: 1.9711x; 1.9711x over previous
#include <cuda_runtime.h>
#include <cuda_bf16.h>
#include <cstdint>

// ===========================================================================
// LEFTNet layer. Edge GEMMs: mma.sync bf16 3-term split, pass-INNER K=32
// chunks, M=64 tiles, 512 threads (16 warps = 2m x 8n, warp tile 32x48,
// acc = 48 regs/thread -> no spills at the 128-reg cap).
// Kernel A: t1 = silu(wgt@iw1+ib1) -> bf16 hi/lo planes (wgt converted
//           in-smem). Kernel B: w2 = t1@iw2+ib2, rbfh = rbf@rw+rb (TC),
//           m = w2*rbfh*xh[src], fused scatter RED. Node GEMMs on FFMA2.
// ===========================================================================

#define NN_MAX 50000
#define NE_MAX 500000

__device__ float g_h1[(size_t)NN_MAX * 128];
__device__ float g_xh[(size_t)NN_MAX * 384];
__device__ __align__(16) __nv_bfloat16 g_t1hi[(size_t)NE_MAX * 384];
__device__ __align__(16) __nv_bfloat16 g_t1lo[(size_t)NE_MAX * 384];
__device__ __align__(16) __nv_bfloat16 g_b1hi[384 * 416];
__device__ __align__(16) __nv_bfloat16 g_b1lo[384 * 416];
__device__ __align__(16) __nv_bfloat16 g_b2hi[384 * 384];
__device__ __align__(16) __nv_bfloat16 g_b2lo[384 * 384];
__device__ __align__(16) __nv_bfloat16 g_rwhi[384 * 32];
__device__ __align__(16) __nv_bfloat16 g_rwlo[384 * 32];

// ---------------------------------------------------------------------------
// helpers
// ---------------------------------------------------------------------------
__device__ __forceinline__ uint32_t smem_u32(const void* p) {
    uint32_t a;
    asm("{ .reg .u64 t; cvta.to.shared.u64 t, %1; cvt.u32.u64 %0, t; }"
        : "=r"(a) : "l"(p));
    return a;
}
__device__ __forceinline__ void cp16(uint32_t s, const void* g) {
    asm volatile("cp.async.cg.shared.global [%0], [%1], 16;"
                 :: "r"(s), "l"(g) : "memory");
}
__device__ __forceinline__ void cp_commit() { asm volatile("cp.async.commit_group;" ::: "memory"); }
__device__ __forceinline__ void cp_wait0()  { asm volatile("cp.async.wait_group 0;" ::: "memory"); }

#define SWZ64(o) ((o) ^ (((o) >> 3) & 0x30))

__device__ __forceinline__ void ldm_x4(uint32_t& r0, uint32_t& r1, uint32_t& r2, uint32_t& r3,
                                       uint32_t addr) {
    asm volatile("ldmatrix.sync.aligned.m8n8.x4.shared.b16 {%0, %1, %2, %3}, [%4];"
                 : "=r"(r0), "=r"(r1), "=r"(r2), "=r"(r3) : "r"(addr));
}
__device__ __forceinline__ void mma_bf16(float* c, const uint32_t* a, const uint32_t* b) {
    asm volatile("mma.sync.aligned.m16n8k16.row.col.f32.bf16.bf16.f32 "
                 "{%0, %1, %2, %3}, {%4, %5, %6, %7}, {%8, %9}, {%0, %1, %2, %3};"
                 : "+f"(c[0]), "+f"(c[1]), "+f"(c[2]), "+f"(c[3])
                 : "r"(a[0]), "r"(a[1]), "r"(a[2]), "r"(a[3]), "r"(b[0]), "r"(b[1]));
}
__device__ __forceinline__ void red_add_v4(float* p, float4 v) {
    asm volatile("red.global.add.v4.f32 [%0], {%1, %2, %3, %4};"
                 :: "l"(p), "f"(v.x), "f"(v.y), "f"(v.z), "f"(v.w) : "memory");
}
__device__ __forceinline__ float silu_f(float v) {
    return v * (1.0f / (1.0f + __expf(-v)));
}
__device__ __forceinline__ void split_bf16(float v, __nv_bfloat16& h, __nv_bfloat16& l) {
    h = __float2bfloat16(v);
    l = __float2bfloat16(v - __bfloat162float(h));
}

// mma over one K=32 chunk (2 k16 steps). Warp tile 32x48, acc[2][6][4].
__device__ __forceinline__ void mma_chunk32(float (*acc)[6][4],
                                            uint32_t Ab, uint32_t Bb,
                                            int wm, int wn,
                                            int a_r, int a_c, int b_r, int b_c)
{
#pragma unroll
    for (int ks = 0; ks < 2; ks++) {
        uint32_t af[2][4];
#pragma unroll
        for (int mt = 0; mt < 2; mt++) {
            int r = wm + mt * 16 + a_r;
            ldm_x4(af[mt][0], af[mt][1], af[mt][2], af[mt][3],
                   Ab + SWZ64(r * 64 + (ks * 2 + a_c) * 16));
        }
#pragma unroll
        for (int np = 0; np < 3; np++) {
            int r = wn + np * 16 + b_r;
            uint32_t b0, b1, b2, b3;
            ldm_x4(b0, b1, b2, b3, Bb + SWZ64(r * 64 + (ks * 2 + b_c) * 16));
            uint32_t bfa[2] = {b0, b1}, bfb[2] = {b2, b3};
#pragma unroll
            for (int mt = 0; mt < 2; mt++) {
                mma_bf16(acc[mt][np * 2 + 0], af[mt], bfa);
                mma_bf16(acc[mt][np * 2 + 1], af[mt], bfb);
            }
        }
    }
}

// ---------------------------------------------------------------------------
// Kernel A: t1 = silu(wgt @ iw1 + ib1) -> bf16 hi/lo planes. M-tile 64.
// stage: A fp32 64x144B [0,9216) ; planes hi [0,4096) lo [4096,8192)
//        Bhi @10240 (24K), Blo @34816 (24K); stage = 59392, x2 buffers.
// ---------------------------------------------------------------------------
#define KA_BHI   10240
#define KA_BLO   34816
#define KA_STAGE 59392
#define KA_SMEM  (2 * KA_STAGE)

__global__ __launch_bounds__(512)
void gemm4_kernel(const float* __restrict__ wgt,
                  const __nv_bfloat16* __restrict__ B1hi,
                  const __nv_bfloat16* __restrict__ B1lo,
                  int E, const float* __restrict__ ib1,
                  __nv_bfloat16* __restrict__ t1hi, __nv_bfloat16* __restrict__ t1lo)
{
    extern __shared__ char dsm[];
    const uint32_t S0 = smem_u32(dsm);
    const int tid  = threadIdx.x;
    const int wid  = tid >> 5;
    const int lane = tid & 31;
    const int row0 = blockIdx.x * 64;

    const int wm  = (wid >> 3) * 32;          // 0 / 32
    const int wn  = (wid & 7) * 48;           // 0..336
    const int gq  = lane >> 2;
    const int tig = lane & 3;
    const int a_r = (lane & 7) + ((lane & 8) ? 8 : 0);
    const int a_c = lane >> 4;
    const int b_r = (lane & 7) + ((lane & 16) ? 8 : 0);
    const int b_c = (lane >> 3) & 1;

    float acc[2][6][4];
#pragma unroll
    for (int i = 0; i < 2; i++)
#pragma unroll
        for (int j = 0; j < 6; j++)
#pragma unroll
            for (int k = 0; k < 4; k++) acc[i][j][k] = 0.0f;

    auto load_chunk = [&](int c) {
        const uint32_t S = S0 + (c & 1) * KA_STAGE;
        const int k0 = c * 32;
        {   // A fp32: 64 rows x 8 x 16B = 512 -> one per thread
            int r = tid >> 3, u = tid & 7;
            int gr = row0 + r; if (gr >= E) gr = E - 1;
            cp16(S + r * 144 + u * 16, wgt + (size_t)gr * 416 + k0 + u * 4);
        }
#pragma unroll
        for (int i = 0; i < 3; i++) {         // Bhi: 384 x 4 units = 1536
            int id = tid + i * 512;
            int r = id >> 2, u = id & 3;
            cp16(S + KA_BHI + SWZ64(r * 64 + u * 16),
                 B1hi + (size_t)r * 416 + k0 + u * 8);
        }
#pragma unroll
        for (int i = 0; i < 3; i++) {         // Blo
            int id = tid + i * 512;
            int r = id >> 2, u = id & 3;
            cp16(S + KA_BLO + SWZ64(r * 64 + u * 16),
                 B1lo + (size_t)r * 416 + k0 + u * 8);
        }
        cp_commit();
    };

    load_chunk(0);

    for (int c = 0; c < 13; c++) {
        const uint32_t S = S0 + (c & 1) * KA_STAGE;
        char* Sc = dsm + (c & 1) * KA_STAGE;

        cp_wait0();
        __syncthreads();
        if (c + 1 < 13) load_chunk(c + 1);

        // in-place convert: thread -> (row = tid>>3, grp = tid&7), 4 floats
        const int cr = tid >> 3, cg = tid & 7;
        float4 v = *(const float4*)(Sc + cr * 144 + cg * 16);
        __syncthreads();                       // all fp32 reads done
        {
            __nv_bfloat16 h0, l0, h1, l1, h2, l2, h3, l3;
            split_bf16(v.x, h0, l0); split_bf16(v.y, h1, l1);
            split_bf16(v.z, h2, l2); split_bf16(v.w, h3, l3);
            uint2 hp, lp;
            hp.x = (uint32_t)__bfloat16_as_ushort(h0) | ((uint32_t)__bfloat16_as_ushort(h1) << 16);
            hp.y = (uint32_t)__bfloat16_as_ushort(h2) | ((uint32_t)__bfloat16_as_ushort(h3) << 16);
            lp.x = (uint32_t)__bfloat16_as_ushort(l0) | ((uint32_t)__bfloat16_as_ushort(l1) << 16);
            lp.y = (uint32_t)__bfloat16_as_ushort(l2) | ((uint32_t)__bfloat16_as_ushort(l3) << 16);
            uint32_t off = SWZ64(cr * 64 + cg * 8);
            *(uint2*)(Sc + off)        = hp;
            *(uint2*)(Sc + 4096 + off) = lp;
        }
        __syncthreads();

        mma_chunk32(acc, S + 0,    S + KA_BHI, wm, wn, a_r, a_c, b_r, b_c);
        mma_chunk32(acc, S + 4096, S + KA_BHI, wm, wn, a_r, a_c, b_r, b_c);
        mma_chunk32(acc, S + 0,    S + KA_BLO, wm, wn, a_r, a_c, b_r, b_c);
    }

    // epilogue: silu -> bf16 hi/lo planes
#pragma unroll
    for (int mt = 0; mt < 2; mt++)
#pragma unroll
        for (int half = 0; half < 2; half++) {
            const int e = row0 + wm + mt * 16 + gq + half * 8;
            if (e >= E) continue;
#pragma unroll
            for (int nt = 0; nt < 6; nt++) {
                const int col = wn + nt * 8 + tig * 2;
                float s0 = silu_f(acc[mt][nt][half * 2 + 0] + ib1[col]);
                float s1 = silu_f(acc[mt][nt][half * 2 + 1] + ib1[col + 1]);
                __nv_bfloat16 h0, l0, h1, l1;
                split_bf16(s0, h0, l0);
                split_bf16(s1, h1, l1);
                *(uint32_t*)&t1hi[(size_t)e * 384 + col] =
                    (uint32_t)__bfloat16_as_ushort(h0) |
                    ((uint32_t)__bfloat16_as_ushort(h1) << 16);
                *(uint32_t*)&t1lo[(size_t)e * 384 + col] =
                    (uint32_t)__bfloat16_as_ushort(l0) |
                    ((uint32_t)__bfloat16_as_ushort(l1) << 16);
            }
        }
}

// ---------------------------------------------------------------------------
// Kernel B: w2 = t1@iw2+ib2; rbfh = rbf@rw+rb (TC); m = w2*rbfh*xh[src];
// scatter RED into dx/dvec. M-tile 64.
// stage: Ahi [0,4096) Alo [4096,8192) Bhi @8192 (24K) Blo @32768 (24K)
//        = 57344 x2 buffers = 114688
// epilogue: m_st 64x388 fp32 [0,99328) (aliases stages); rbf @99328
//           (fp32 9216 -> planes 4K+4K); rw planes @108544 (24K+24K)
// ---------------------------------------------------------------------------
#define KB_BHI   8192
#define KB_BLO   32768
#define KB_STAGE 57344
#define KB_RF    99328
#define KB_RW    108544
#define KB_SMEM  (108544 + 49152)

__global__ __launch_bounds__(512)
void gemm5_kernel(const __nv_bfloat16* __restrict__ t1hi,
                  const __nv_bfloat16* __restrict__ t1lo,
                  const __nv_bfloat16* __restrict__ B2hi,
                  const __nv_bfloat16* __restrict__ B2lo,
                  const __nv_bfloat16* __restrict__ RWhi,
                  const __nv_bfloat16* __restrict__ RWlo,
                  const float* __restrict__ rbf,
                  const float* __restrict__ ib2, const float* __restrict__ rb,
                  const float* __restrict__ xh,
                  const int* __restrict__ ei, int E,
                  const float* __restrict__ vec, const float* __restrict__ ev,
                  float* __restrict__ dx, float* __restrict__ dvec)
{
    extern __shared__ char dsm[];
    const uint32_t S0 = smem_u32(dsm);
    float* m_st = (float*)dsm;                 // stride 388
    const int tid  = threadIdx.x;
    const int wid  = tid >> 5;
    const int lane = tid & 31;
    const int row0 = blockIdx.x * 64;

    const int wm  = (wid >> 3) * 32;
    const int wn  = (wid & 7) * 48;
    const int gq  = lane >> 2;
    const int tig = lane & 3;
    const int a_r = (lane & 7) + ((lane & 8) ? 8 : 0);
    const int a_c = lane >> 4;
    const int b_r = (lane & 7) + ((lane & 16) ? 8 : 0);
    const int b_c = (lane >> 3) & 1;

    float acc[2][6][4];
#pragma unroll
    for (int i = 0; i < 2; i++)
#pragma unroll
        for (int j = 0; j < 6; j++)
#pragma unroll
            for (int k = 0; k < 4; k++) acc[i][j][k] = 0.0f;

    auto load_chunk = [&](int c) {
        const uint32_t S = S0 + (c & 1) * KB_STAGE;
        const int k0 = c * 32;
        {   // A planes: 64 rows x 4 units x 2 planes = 512 -> one per thread
            int plane = tid >> 8;              // 0 = hi, 1 = lo
            int rem   = tid & 255;
            int r = rem >> 2, u = rem & 3;
            int gr = row0 + r; if (gr >= E) gr = E - 1;
            const __nv_bfloat16* Ap = plane ? t1lo : t1hi;
            cp16(S + plane * 4096 + SWZ64(r * 64 + u * 16),
                 Ap + (size_t)gr * 384 + k0 + u * 8);
        }
#pragma unroll
        for (int i = 0; i < 3; i++) {
            int id = tid + i * 512;
            int r = id >> 2, u = id & 3;
            cp16(S + KB_BHI + SWZ64(r * 64 + u * 16),
                 B2hi + (size_t)r * 384 + k0 + u * 8);
        }
#pragma unroll
        for (int i = 0; i < 3; i++) {
            int id = tid + i * 512;
            int r = id >> 2, u = id & 3;
            cp16(S + KB_BLO + SWZ64(r * 64 + u * 16),
                 B2lo + (size_t)r * 384 + k0 + u * 8);
        }
        cp_commit();
    };

    load_chunk(0);
    for (int c = 0; c < 12; c++) {
        const uint32_t S = S0 + (c & 1) * KB_STAGE;
        cp_wait0();
        __syncthreads();
        if (c + 1 < 12) load_chunk(c + 1);
        mma_chunk32(acc, S + 0,    S + KB_BHI, wm, wn, a_r, a_c, b_r, b_c);
        mma_chunk32(acc, S + 4096, S + KB_BHI, wm, wn, a_r, a_c, b_r, b_c);
        mma_chunk32(acc, S + 0,    S + KB_BLO, wm, wn, a_r, a_c, b_r, b_c);
        __syncthreads();
    }

    // ---- start rbf/rw loads (stage regions free after last sync) ----
    {   // rbf fp32: 64 rows x 8 x 16B = 512
        int r = tid >> 3, u = tid & 7;
        int gr = row0 + r; if (gr >= E) gr = E - 1;
        cp16(S0 + KB_RF + r * 144 + u * 16, rbf + (size_t)gr * 32 + u * 4);
    }
#pragma unroll
    for (int i = 0; i < 6; i++) {              // rw planes: 384 x 4 x 2 = 3072
        int id = tid + i * 512;
        int plane = id / 1536;
        int rem   = id - plane * 1536;
        int r = rem >> 2, u = rem & 3;
        const __nv_bfloat16* Rp = plane ? RWlo : RWhi;
        cp16(S0 + KB_RW + plane * 24576 + SWZ64(r * 64 + u * 16),
             Rp + (size_t)r * 32 + u * 8);
    }
    cp_commit();

    // stage w2 + ib2 into m_st (aliases stage buffers; mainloop reads done)
#pragma unroll
    for (int mt = 0; mt < 2; mt++)
#pragma unroll
        for (int half = 0; half < 2; half++) {
            const int er = wm + mt * 16 + gq + half * 8;
#pragma unroll
            for (int nt = 0; nt < 6; nt++) {
                const int col = wn + nt * 8 + tig * 2;
                float2 o;
                o.x = acc[mt][nt][half * 2 + 0] + ib2[col];
                o.y = acc[mt][nt][half * 2 + 1] + ib2[col + 1];
                *(float2*)&m_st[er * 388 + col] = o;
            }
        }

    // ---- rbfh: rbf @ rw^T (3-pass) ----
#pragma unroll
    for (int i = 0; i < 2; i++)
#pragma unroll
        for (int j = 0; j < 6; j++)
#pragma unroll
            for (int k = 0; k < 4; k++) acc[i][j][k] = 0.0f;

    cp_wait0(); __syncthreads();
    {   // convert rbf fp32 -> hi/lo planes in place
        const int cr = tid >> 3, cg = tid & 7;
        float4 v = *(const float4*)(dsm + KB_RF + cr * 144 + cg * 16);
        __syncthreads();
        __nv_bfloat16 h0, l0, h1, l1, h2, l2, h3, l3;
        split_bf16(v.x, h0, l0); split_bf16(v.y, h1, l1);
        split_bf16(v.z, h2, l2); split_bf16(v.w, h3, l3);
        uint2 hp, lp;
        hp.x = (uint32_t)__bfloat16_as_ushort(h0) | ((uint32_t)__bfloat16_as_ushort(h1) << 16);
        hp.y = (uint32_t)__bfloat16_as_ushort(h2) | ((uint32_t)__bfloat16_as_ushort(h3) << 16);
        lp.x = (uint32_t)__bfloat16_as_ushort(l0) | ((uint32_t)__bfloat16_as_ushort(l1) << 16);
        lp.y = (uint32_t)__bfloat16_as_ushort(l2) | ((uint32_t)__bfloat16_as_ushort(l3) << 16);
        uint32_t off = SWZ64(cr * 64 + cg * 8);
        *(uint2*)(dsm + KB_RF + off)        = hp;
        *(uint2*)(dsm + KB_RF + 4096 + off) = lp;
        __syncthreads();
    }
    mma_chunk32(acc, S0 + KB_RF,        S0 + KB_RW,         wm, wn, a_r, a_c, b_r, b_c);
    mma_chunk32(acc, S0 + KB_RF + 4096, S0 + KB_RW,         wm, wn, a_r, a_c, b_r, b_c);
    mma_chunk32(acc, S0 + KB_RF,        S0 + KB_RW + 24576, wm, wn, a_r, a_c, b_r, b_c);

    // multiply own cells: m_st *= (rbfh + rb)
#pragma unroll
    for (int mt = 0; mt < 2; mt++)
#pragma unroll
        for (int half = 0; half < 2; half++) {
            const int er = wm + mt * 16 + gq + half * 8;
#pragma unroll
            for (int nt = 0; nt < 6; nt++) {
                const int col = wn + nt * 8 + tig * 2;
                float2 o = *(float2*)&m_st[er * 388 + col];
                o.x *= acc[mt][nt][half * 2 + 0] + rb[col];
                o.y *= acc[mt][nt][half * 2 + 1] + rb[col + 1];
                *(float2*)&m_st[er * 388 + col] = o;
            }
        }
    __syncthreads();

    // ---- scatter: 16 warps x 4 edges ----
    const float is3 = 0.57735026918962576f;   // 1/sqrt(3)
    const float ish = 0.08838834764831845f;   // 1/sqrt(128)
#pragma unroll
    for (int i = 0; i < 4; i++) {
        const int er = wid * 4 + i;
        const int e  = row0 + er;
        if (e >= E) continue;
        const int s = ei[e];
        const int d = ei[E + e];

        const float* st = m_st + er * 388;
        float4 a0 = *(const float4*)&st[lane * 4];
        float4 a1 = *(const float4*)&st[128 + lane * 4];
        float4 a2 = *(const float4*)&st[256 + lane * 4];

        const float* xr = xh + (size_t)s * 384;
        float4 x0 = *(const float4*)&xr[lane * 4];
        float4 x1 = *(const float4*)&xr[128 + lane * 4];
        float4 x2 = *(const float4*)&xr[256 + lane * 4];

        float4 xm, h2, h3;
        xm.x = a0.x * x0.x;  xm.y = a0.y * x0.y;
        xm.z = a0.z * x0.z;  xm.w = a0.w * x0.w;
        h2.x = a1.x * x1.x * is3;  h2.y = a1.y * x1.y * is3;
        h2.z = a1.z * x1.z * is3;  h2.w = a1.w * x1.w * is3;
        h3.x = a2.x * x2.x;  h3.y = a2.y * x2.y;
        h3.z = a2.z * x2.z;  h3.w = a2.w * x2.w;

        red_add_v4(dx + (size_t)d * 128 + lane * 4, xm);

        float evd[3];
        evd[0] = __ldg(&ev[(size_t)e * 3 + 0]);
        evd[1] = __ldg(&ev[(size_t)e * 3 + 1]);
        evd[2] = __ldg(&ev[(size_t)e * 3 + 2]);
        const float4* v4 = (const float4*)(vec + (size_t)s * 384);
#pragma unroll
        for (int t = 0; t < 3; t++) {
            float4 v = v4[t * 32 + lane];
            float4 o;
            o.x = (v.x * h2.x + h3.x * evd[t]) * ish;
            o.y = (v.y * h2.y + h3.y * evd[t]) * ish;
            o.z = (v.z * h2.z + h3.z * evd[t]) * ish;
            o.w = (v.w * h2.w + h3.w * evd[t]) * ish;
            red_add_v4(dvec + ((size_t)d * 3 + t) * 128 + lane * 4, o);
        }
    }
}

// ---------------------------------------------------------------------------
// Transpose+split weights: src [K,N] fp32 -> hi/lo [N,K] bf16
// ---------------------------------------------------------------------------
__global__ void splitT(const float* __restrict__ src,
                       __nv_bfloat16* __restrict__ hi,
                       __nv_bfloat16* __restrict__ lo,
                       int K, int N)
{
    int t = blockIdx.x * blockDim.x + threadIdx.x;
    if (t >= N * K) return;
    int n = t / K, k = t - n * K;
    float v = src[(size_t)k * N + n];
    __nv_bfloat16 h, l;
    h = __float2bfloat16(v);
    l = __float2bfloat16(v - __bfloat162float(h));
    hi[t] = h;
    lo[t] = l;
}

// ---------------------------------------------------------------------------
// FFMA2 SGEMM for the node GEMMs
// ---------------------------------------------------------------------------
#define BM 128
#define BN 128
#define BK 16

__device__ __forceinline__ unsigned long long pack2(float lo, float hi) {
    unsigned long long r;
    asm("mov.b64 %0, {%1, %2};" : "=l"(r) : "f"(lo), "f"(hi));
    return r;
}
__device__ __forceinline__ void unpack2(unsigned long long v, float& lo, float& hi) {
    asm("mov.b64 {%0, %1}, %2;" : "=f"(lo), "=f"(hi) : "l"(v));
}
__device__ __forceinline__ void ffma2(unsigned long long& d,
                                      unsigned long long a, unsigned long long b) {
    asm("fma.rn.f32x2 %0, %1, %2, %0;" : "+l"(d) : "l"(a), "l"(b));
}

template<bool SILU>
__global__ __launch_bounds__(256, 2)
void sgemm_bias_act(const float* __restrict__ A, const float* __restrict__ B,
                    const float* __restrict__ bias, float* __restrict__ C,
                    int M, int N, int K)
{
    __shared__ float As[BK][BM + 4];
    __shared__ float Bs[BK][BN];

    const int tid  = threadIdx.x;
    const int tx   = tid & 15;
    const int ty   = tid >> 4;
    const int row0 = blockIdx.y * BM;
    const int col0 = blockIdx.x * BN;

    unsigned long long acc2[8][4];
#pragma unroll
    for (int i = 0; i < 8; i++)
#pragma unroll
        for (int j = 0; j < 4; j++) acc2[i][j] = 0ull;

    const int a_row = tid >> 2;
    const int a_seg = tid & 3;
    const int b_kk  = tid >> 5;
    const int b_c4  = (tid & 31) << 2;

    for (int k0 = 0; k0 < K; k0 += BK) {
#pragma unroll
        for (int it = 0; it < 2; it++) {
            int r  = a_row + it * 64;
            int gr = row0 + r;
            float4 v = make_float4(0.f, 0.f, 0.f, 0.f);
            if (gr < M)
                v = *(const float4*)&A[(size_t)gr * K + k0 + a_seg * 4];
            As[a_seg * 4 + 0][r] = v.x;
            As[a_seg * 4 + 1][r] = v.y;
            As[a_seg * 4 + 2][r] = v.z;
            As[a_seg * 4 + 3][r] = v.w;
        }
#pragma unroll
        for (int it = 0; it < 2; it++) {
            int kk = b_kk + it * 8;
            *(float4*)&Bs[kk][b_c4] =
                *(const float4*)&B[(size_t)(k0 + kk) * N + col0 + b_c4];
        }
        __syncthreads();

#pragma unroll
        for (int kk = 0; kk < BK; kk++) {
            float4 a0 = *(const float4*)&As[kk][ty * 4];
            float4 a1 = *(const float4*)&As[kk][64 + ty * 4];
            float4 b0 = *(const float4*)&Bs[kk][tx * 4];
            float4 b1 = *(const float4*)&Bs[kk][64 + tx * 4];
            unsigned long long bp[4] = {
                pack2(b0.x, b0.y), pack2(b0.z, b0.w),
                pack2(b1.x, b1.y), pack2(b1.z, b1.w)
            };
            float av[8] = {a0.x, a0.y, a0.z, a0.w, a1.x, a1.y, a1.z, a1.w};
#pragma unroll
            for (int i = 0; i < 8; i++) {
                unsigned long long ap = pack2(av[i], av[i]);
#pragma unroll
                for (int jp = 0; jp < 4; jp++)
                    ffma2(acc2[i][jp], ap, bp[jp]);
            }
        }
        __syncthreads();
    }

#pragma unroll
    for (int i = 0; i < 8; i++) {
        int r  = (i < 4) ? (ty * 4 + i) : (64 + ty * 4 + (i - 4));
        int gr = row0 + r;
        if (gr >= M) continue;
#pragma unroll
        for (int jg = 0; jg < 2; jg++) {
            int c  = (jg == 0) ? (tx * 4) : (64 + tx * 4);
            int gc = col0 + c;
            float4 bi = *(const float4*)&bias[gc];
            float4 o;
            unpack2(acc2[i][jg * 2 + 0], o.x, o.y);
            unpack2(acc2[i][jg * 2 + 1], o.z, o.w);
            o.x += bi.x; o.y += bi.y; o.z += bi.z; o.w += bi.w;
            if (SILU) {
                o.x = silu_f(o.x); o.y = silu_f(o.y);
                o.z = silu_f(o.z); o.w = silu_f(o.w);
            }
            *(float4*)&C[(size_t)gr * N + gc] = o;
        }
    }
}

// ---------------------------------------------------------------------------
// Launch
// ---------------------------------------------------------------------------
extern "C" void kernel_launch(void* const* d_in, const int* in_sizes, int n_in,
                              void* d_out, int out_size)
{
    const float* x    = (const float*)d_in[0];
    const float* vec  = (const float*)d_in[1];
    const int*   ei   = (const int*)  d_in[2];
    const float* rbf  = (const float*)d_in[3];
    const float* wgt  = (const float*)d_in[4];
    const float* ev   = (const float*)d_in[5];
    const float* xw1  = (const float*)d_in[6];
    const float* xb1  = (const float*)d_in[7];
    const float* xw2  = (const float*)d_in[8];
    const float* xb2  = (const float*)d_in[9];
    const float* rw   = (const float*)d_in[10];
    const float* rb   = (const float*)d_in[11];
    const float* iw1  = (const float*)d_in[12];
    const float* ib1  = (const float*)d_in[13];
    const float* iw2  = (const float*)d_in[14];
    const float* ib2  = (const float*)d_in[15];

    const int nn = in_sizes[0] / 128;
    const int ne = in_sizes[2] / 2;

    float* out  = (float*)d_out;
    float* dx   = out;
    float* dvec = out + (size_t)nn * 128;

    float *p_h1, *p_xh;
    __nv_bfloat16 *p_t1hi, *p_t1lo, *p_b1hi, *p_b1lo, *p_b2hi, *p_b2lo, *p_rwhi, *p_rwlo;
    cudaGetSymbolAddress((void**)&p_h1,  g_h1);
    cudaGetSymbolAddress((void**)&p_xh,  g_xh);
    cudaGetSymbolAddress((void**)&p_t1hi, g_t1hi);
    cudaGetSymbolAddress((void**)&p_t1lo, g_t1lo);
    cudaGetSymbolAddress((void**)&p_b1hi, g_b1hi);
    cudaGetSymbolAddress((void**)&p_b1lo, g_b1lo);
    cudaGetSymbolAddress((void**)&p_b2hi, g_b2hi);
    cudaGetSymbolAddress((void**)&p_b2lo, g_b2lo);
    cudaGetSymbolAddress((void**)&p_rwhi, g_rwhi);
    cudaGetSymbolAddress((void**)&p_rwlo, g_rwlo);

    cudaFuncSetAttribute(gemm4_kernel,
                         cudaFuncAttributeMaxDynamicSharedMemorySize, KA_SMEM);
    cudaFuncSetAttribute(gemm5_kernel,
                         cudaFuncAttributeMaxDynamicSharedMemorySize, KB_SMEM);

    cudaMemsetAsync(d_out, 0, (size_t)out_size * sizeof(float));

    dim3 blk(256);

    // weight conversions (tiny)
    splitT<<<(384 * 416 + 255) / 256, blk>>>(iw1, p_b1hi, p_b1lo, 416, 384);
    splitT<<<(384 * 384 + 255) / 256, blk>>>(iw2, p_b2hi, p_b2lo, 384, 384);
    splitT<<<(384 * 32  + 255) / 256, blk>>>(rw,  p_rwhi, p_rwlo, 32,  384);

    // node projection (FFMA2): xh = silu(x@xw1+xb1)@xw2+xb2
    sgemm_bias_act<true ><<<dim3(1, (nn + BM - 1) / BM), blk>>>(x,    xw1, xb1, p_h1, nn, 128, 128);
    sgemm_bias_act<false><<<dim3(3, (nn + BM - 1) / BM), blk>>>(p_h1, xw2, xb2, p_xh, nn, 384, 128);

    const int mtiles = (ne + 63) / 64;
    gemm4_kernel<<<mtiles, 512, KA_SMEM>>>(wgt, p_b1hi, p_b1lo, ne, ib1, p_t1hi, p_t1lo);
    gemm5_kernel<<<mtiles, 512, KB_SMEM>>>(p_t1hi, p_t1lo, p_b2hi, p_b2lo,
                                           p_rwhi, p_rwlo, rbf, ib2, rb,
                                           p_xh, ei, ne, vec, ev, dx, dvec);
}

// round 15
// speedup vs baseline: 2.4702x; 1.2532x over previous
#include <cuda_runtime.h>
#include <cuda_fp16.h>
#include <cstdint>

// ===========================================================================
// LEFTNet layer. Edge GEMMs: mma.sync fp16 2-pass (A split hi/lo fp16,
// B single fp16), pass-INNER K=32 chunks, M=64 tiles, 512 threads
// (16 warps = 2m x 8n, warp tile 32x48, acc = 48 regs -> no spills).
// Kernel A: t1 = silu(wgt@iw1+ib1) -> fp16 hi/lo planes.
// Kernel B: w2 = t1@iw2+ib2, rbfh = rbf@rw+rb (TC), m = w2*rbfh*xh[src],
//           fused scatter RED. Node GEMMs on FFMA2.
// ===========================================================================

#define NN_MAX 50000
#define NE_MAX 500000

__device__ float g_h1[(size_t)NN_MAX * 128];
__device__ float g_xh[(size_t)NN_MAX * 384];
__device__ __align__(16) __half g_t1hi[(size_t)NE_MAX * 384];
__device__ __align__(16) __half g_t1lo[(size_t)NE_MAX * 384];
__device__ __align__(16) __half g_b1[384 * 416];
__device__ __align__(16) __half g_b2[384 * 384];
__device__ __align__(16) __half g_rw[384 * 32];

// ---------------------------------------------------------------------------
// helpers
// ---------------------------------------------------------------------------
__device__ __forceinline__ uint32_t smem_u32(const void* p) {
    uint32_t a;
    asm("{ .reg .u64 t; cvta.to.shared.u64 t, %1; cvt.u32.u64 %0, t; }"
        : "=r"(a) : "l"(p));
    return a;
}
__device__ __forceinline__ void cp16(uint32_t s, const void* g) {
    asm volatile("cp.async.cg.shared.global [%0], [%1], 16;"
                 :: "r"(s), "l"(g) : "memory");
}
__device__ __forceinline__ void cp_commit() { asm volatile("cp.async.commit_group;" ::: "memory"); }
__device__ __forceinline__ void cp_wait0()  { asm volatile("cp.async.wait_group 0;" ::: "memory"); }

#define SWZ64(o) ((o) ^ (((o) >> 3) & 0x30))

__device__ __forceinline__ void ldm_x4(uint32_t& r0, uint32_t& r1, uint32_t& r2, uint32_t& r3,
                                       uint32_t addr) {
    asm volatile("ldmatrix.sync.aligned.m8n8.x4.shared.b16 {%0, %1, %2, %3}, [%4];"
                 : "=r"(r0), "=r"(r1), "=r"(r2), "=r"(r3) : "r"(addr));
}
__device__ __forceinline__ void mma_f16(float* c, const uint32_t* a, const uint32_t* b) {
    asm volatile("mma.sync.aligned.m16n8k16.row.col.f32.f16.f16.f32 "
                 "{%0, %1, %2, %3}, {%4, %5, %6, %7}, {%8, %9}, {%0, %1, %2, %3};"
                 : "+f"(c[0]), "+f"(c[1]), "+f"(c[2]), "+f"(c[3])
                 : "r"(a[0]), "r"(a[1]), "r"(a[2]), "r"(a[3]), "r"(b[0]), "r"(b[1]));
}
__device__ __forceinline__ void red_add_v4(float* p, float4 v) {
    asm volatile("red.global.add.v4.f32 [%0], {%1, %2, %3, %4};"
                 :: "l"(p), "f"(v.x), "f"(v.y), "f"(v.z), "f"(v.w) : "memory");
}
__device__ __forceinline__ float silu_f(float v) {
    return v * (1.0f / (1.0f + __expf(-v)));
}
__device__ __forceinline__ void split_f16(float v, __half& h, __half& l) {
    h = __float2half_rn(v);
    l = __float2half_rn(v - __half2float(h));
}

// mma over one K=32 chunk (2 k16 steps). Warp tile 32x48, acc[2][6][4].
__device__ __forceinline__ void mma_chunk32(float (*acc)[6][4],
                                            uint32_t Ab, uint32_t Bb,
                                            int wm, int wn,
                                            int a_r, int a_c, int b_r, int b_c)
{
#pragma unroll
    for (int ks = 0; ks < 2; ks++) {
        uint32_t af[2][4];
#pragma unroll
        for (int mt = 0; mt < 2; mt++) {
            int r = wm + mt * 16 + a_r;
            ldm_x4(af[mt][0], af[mt][1], af[mt][2], af[mt][3],
                   Ab + SWZ64(r * 64 + (ks * 2 + a_c) * 16));
        }
#pragma unroll
        for (int np = 0; np < 3; np++) {
            int r = wn + np * 16 + b_r;
            uint32_t b0, b1, b2, b3;
            ldm_x4(b0, b1, b2, b3, Bb + SWZ64(r * 64 + (ks * 2 + b_c) * 16));
            uint32_t bfa[2] = {b0, b1}, bfb[2] = {b2, b3};
#pragma unroll
            for (int mt = 0; mt < 2; mt++) {
                mma_f16(acc[mt][np * 2 + 0], af[mt], bfa);
                mma_f16(acc[mt][np * 2 + 1], af[mt], bfb);
            }
        }
    }
}

// ---------------------------------------------------------------------------
// Kernel A: t1 = silu(wgt @ iw1 + ib1) -> fp16 hi/lo planes. M-tile 64.
// stage: A fp32 64x144B [0,9216) -> planes hi [0,4096) lo [4096,8192)
//        B @10240 (24K); stage = 34816, x2.
// ---------------------------------------------------------------------------
#define KA_B     10240
#define KA_STAGE 34816
#define KA_SMEM  (2 * KA_STAGE)

__global__ __launch_bounds__(512)
void gemm4_kernel(const float* __restrict__ wgt,
                  const __half* __restrict__ B1,
                  int E, const float* __restrict__ ib1,
                  __half* __restrict__ t1hi, __half* __restrict__ t1lo)
{
    extern __shared__ char dsm[];
    const uint32_t S0 = smem_u32(dsm);
    const int tid  = threadIdx.x;
    const int wid  = tid >> 5;
    const int lane = tid & 31;
    const int row0 = blockIdx.x * 64;

    const int wm  = (wid >> 3) * 32;
    const int wn  = (wid & 7) * 48;
    const int gq  = lane >> 2;
    const int tig = lane & 3;
    const int a_r = (lane & 7) + ((lane & 8) ? 8 : 0);
    const int a_c = lane >> 4;
    const int b_r = (lane & 7) + ((lane & 16) ? 8 : 0);
    const int b_c = (lane >> 3) & 1;

    float acc[2][6][4];
#pragma unroll
    for (int i = 0; i < 2; i++)
#pragma unroll
        for (int j = 0; j < 6; j++)
#pragma unroll
            for (int k = 0; k < 4; k++) acc[i][j][k] = 0.0f;

    auto load_chunk = [&](int c) {
        const uint32_t S = S0 + (c & 1) * KA_STAGE;
        const int k0 = c * 32;
        {   // A fp32: 64 rows x 8 x 16B = 512 -> one per thread
            int r = tid >> 3, u = tid & 7;
            int gr = row0 + r; if (gr >= E) gr = E - 1;
            cp16(S + r * 144 + u * 16, wgt + (size_t)gr * 416 + k0 + u * 4);
        }
#pragma unroll
        for (int i = 0; i < 3; i++) {         // B: 384 x 4 units = 1536
            int id = tid + i * 512;
            int r = id >> 2, u = id & 3;
            cp16(S + KA_B + SWZ64(r * 64 + u * 16),
                 B1 + (size_t)r * 416 + k0 + u * 8);
        }
        cp_commit();
    };

    load_chunk(0);

    for (int c = 0; c < 13; c++) {
        const uint32_t S = S0 + (c & 1) * KA_STAGE;
        char* Sc = dsm + (c & 1) * KA_STAGE;

        cp_wait0();
        __syncthreads();
        if (c + 1 < 13) load_chunk(c + 1);

        // in-place convert: thread -> (row = tid>>3, grp = tid&7), 4 floats
        const int cr = tid >> 3, cg = tid & 7;
        float4 v = *(const float4*)(Sc + cr * 144 + cg * 16);
        __syncthreads();
        {
            __half h0, l0, h1, l1, h2, l2, h3, l3;
            split_f16(v.x, h0, l0); split_f16(v.y, h1, l1);
            split_f16(v.z, h2, l2); split_f16(v.w, h3, l3);
            uint2 hp, lp;
            hp.x = (uint32_t)__half_as_ushort(h0) | ((uint32_t)__half_as_ushort(h1) << 16);
            hp.y = (uint32_t)__half_as_ushort(h2) | ((uint32_t)__half_as_ushort(h3) << 16);
            lp.x = (uint32_t)__half_as_ushort(l0) | ((uint32_t)__half_as_ushort(l1) << 16);
            lp.y = (uint32_t)__half_as_ushort(l2) | ((uint32_t)__half_as_ushort(l3) << 16);
            uint32_t off = SWZ64(cr * 64 + cg * 8);
            *(uint2*)(Sc + off)        = hp;
            *(uint2*)(Sc + 4096 + off) = lp;
        }
        __syncthreads();

        mma_chunk32(acc, S + 0,    S + KA_B, wm, wn, a_r, a_c, b_r, b_c); // hi*B
        mma_chunk32(acc, S + 4096, S + KA_B, wm, wn, a_r, a_c, b_r, b_c); // lo*B
    }

    // epilogue: silu -> fp16 hi/lo planes
#pragma unroll
    for (int mt = 0; mt < 2; mt++)
#pragma unroll
        for (int half = 0; half < 2; half++) {
            const int e = row0 + wm + mt * 16 + gq + half * 8;
            if (e >= E) continue;
#pragma unroll
            for (int nt = 0; nt < 6; nt++) {
                const int col = wn + nt * 8 + tig * 2;
                float s0 = silu_f(acc[mt][nt][half * 2 + 0] + ib1[col]);
                float s1 = silu_f(acc[mt][nt][half * 2 + 1] + ib1[col + 1]);
                __half h0, l0, h1, l1;
                split_f16(s0, h0, l0);
                split_f16(s1, h1, l1);
                *(uint32_t*)&t1hi[(size_t)e * 384 + col] =
                    (uint32_t)__half_as_ushort(h0) |
                    ((uint32_t)__half_as_ushort(h1) << 16);
                *(uint32_t*)&t1lo[(size_t)e * 384 + col] =
                    (uint32_t)__half_as_ushort(l0) |
                    ((uint32_t)__half_as_ushort(l1) << 16);
            }
        }
}

// ---------------------------------------------------------------------------
// Kernel B: w2 = t1@iw2+ib2; rbfh = rbf@rw+rb (TC, 2-pass); m = w2*rbfh*
// xh[src]; scatter RED. M-tile 64.
// stage: Ahi [0,4096) Alo [4096,8192) B @8192 (24K) = 32768, x2 = 65536
// epilogue: m_st 64x388 fp32 [0,99328) (aliases); rbf @99328 (fp32 9216 ->
//           planes 4K+4K); rw plane @108544 (24K). total 133120.
// ---------------------------------------------------------------------------
#define KB_B     8192
#define KB_STAGE 32768
#define KB_RF    99328
#define KB_RW    108544
#define KB_SMEM  (108544 + 24576)

__global__ __launch_bounds__(512)
void gemm5_kernel(const __half* __restrict__ t1hi,
                  const __half* __restrict__ t1lo,
                  const __half* __restrict__ B2,
                  const __half* __restrict__ RW,
                  const float* __restrict__ rbf,
                  const float* __restrict__ ib2, const float* __restrict__ rb,
                  const float* __restrict__ xh,
                  const int* __restrict__ ei, int E,
                  const float* __restrict__ vec, const float* __restrict__ ev,
                  float* __restrict__ dx, float* __restrict__ dvec)
{
    extern __shared__ char dsm[];
    const uint32_t S0 = smem_u32(dsm);
    float* m_st = (float*)dsm;                 // stride 388
    const int tid  = threadIdx.x;
    const int wid  = tid >> 5;
    const int lane = tid & 31;
    const int row0 = blockIdx.x * 64;

    const int wm  = (wid >> 3) * 32;
    const int wn  = (wid & 7) * 48;
    const int gq  = lane >> 2;
    const int tig = lane & 3;
    const int a_r = (lane & 7) + ((lane & 8) ? 8 : 0);
    const int a_c = lane >> 4;
    const int b_r = (lane & 7) + ((lane & 16) ? 8 : 0);
    const int b_c = (lane >> 3) & 1;

    float acc[2][6][4];
#pragma unroll
    for (int i = 0; i < 2; i++)
#pragma unroll
        for (int j = 0; j < 6; j++)
#pragma unroll
            for (int k = 0; k < 4; k++) acc[i][j][k] = 0.0f;

    auto load_chunk = [&](int c) {
        const uint32_t S = S0 + (c & 1) * KB_STAGE;
        const int k0 = c * 32;
        {   // A planes: 64 rows x 4 units x 2 planes = 512 -> one per thread
            int plane = tid >> 8;
            int rem   = tid & 255;
            int r = rem >> 2, u = rem & 3;
            int gr = row0 + r; if (gr >= E) gr = E - 1;
            const __half* Ap = plane ? t1lo : t1hi;
            cp16(S + plane * 4096 + SWZ64(r * 64 + u * 16),
                 Ap + (size_t)gr * 384 + k0 + u * 8);
        }
#pragma unroll
        for (int i = 0; i < 3; i++) {
            int id = tid + i * 512;
            int r = id >> 2, u = id & 3;
            cp16(S + KB_B + SWZ64(r * 64 + u * 16),
                 B2 + (size_t)r * 384 + k0 + u * 8);
        }
        cp_commit();
    };

    load_chunk(0);
    for (int c = 0; c < 12; c++) {
        const uint32_t S = S0 + (c & 1) * KB_STAGE;
        cp_wait0();
        __syncthreads();
        if (c + 1 < 12) load_chunk(c + 1);
        mma_chunk32(acc, S + 0,    S + KB_B, wm, wn, a_r, a_c, b_r, b_c);
        mma_chunk32(acc, S + 4096, S + KB_B, wm, wn, a_r, a_c, b_r, b_c);
        __syncthreads();
    }

    // ---- start rbf/rw loads (stage regions free) ----
    {   // rbf fp32: 64 rows x 8 x 16B = 512
        int r = tid >> 3, u = tid & 7;
        int gr = row0 + r; if (gr >= E) gr = E - 1;
        cp16(S0 + KB_RF + r * 144 + u * 16, rbf + (size_t)gr * 32 + u * 4);
    }
#pragma unroll
    for (int i = 0; i < 3; i++) {              // rw plane: 384 x 4 = 1536
        int id = tid + i * 512;
        int r = id >> 2, u = id & 3;
        cp16(S0 + KB_RW + SWZ64(r * 64 + u * 16), RW + (size_t)r * 32 + u * 8);
    }
    cp_commit();

    // stage w2 + ib2 into m_st (aliases stage buffers)
#pragma unroll
    for (int mt = 0; mt < 2; mt++)
#pragma unroll
        for (int half = 0; half < 2; half++) {
            const int er = wm + mt * 16 + gq + half * 8;
#pragma unroll
            for (int nt = 0; nt < 6; nt++) {
                const int col = wn + nt * 8 + tig * 2;
                float2 o;
                o.x = acc[mt][nt][half * 2 + 0] + ib2[col];
                o.y = acc[mt][nt][half * 2 + 1] + ib2[col + 1];
                *(float2*)&m_st[er * 388 + col] = o;
            }
        }

    // ---- rbfh: rbf @ rw^T (2-pass) ----
#pragma unroll
    for (int i = 0; i < 2; i++)
#pragma unroll
        for (int j = 0; j < 6; j++)
#pragma unroll
            for (int k = 0; k < 4; k++) acc[i][j][k] = 0.0f;

    cp_wait0(); __syncthreads();
    {   // convert rbf fp32 -> hi/lo planes in place
        const int cr = tid >> 3, cg = tid & 7;
        float4 v = *(const float4*)(dsm + KB_RF + cr * 144 + cg * 16);
        __syncthreads();
        __half h0, l0, h1, l1, h2, l2, h3, l3;
        split_f16(v.x, h0, l0); split_f16(v.y, h1, l1);
        split_f16(v.z, h2, l2); split_f16(v.w, h3, l3);
        uint2 hp, lp;
        hp.x = (uint32_t)__half_as_ushort(h0) | ((uint32_t)__half_as_ushort(h1) << 16);
        hp.y = (uint32_t)__half_as_ushort(h2) | ((uint32_t)__half_as_ushort(h3) << 16);
        lp.x = (uint32_t)__half_as_ushort(l0) | ((uint32_t)__half_as_ushort(l1) << 16);
        lp.y = (uint32_t)__half_as_ushort(l2) | ((uint32_t)__half_as_ushort(l3) << 16);
        uint32_t off = SWZ64(cr * 64 + cg * 8);
        *(uint2*)(dsm + KB_RF + off)        = hp;
        *(uint2*)(dsm + KB_RF + 4096 + off) = lp;
        __syncthreads();
    }
    mma_chunk32(acc, S0 + KB_RF,        S0 + KB_RW, wm, wn, a_r, a_c, b_r, b_c);
    mma_chunk32(acc, S0 + KB_RF + 4096, S0 + KB_RW, wm, wn, a_r, a_c, b_r, b_c);

    // multiply own cells: m_st *= (rbfh + rb)
#pragma unroll
    for (int mt = 0; mt < 2; mt++)
#pragma unroll
        for (int half = 0; half < 2; half++) {
            const int er = wm + mt * 16 + gq + half * 8;
#pragma unroll
            for (int nt = 0; nt < 6; nt++) {
                const int col = wn + nt * 8 + tig * 2;
                float2 o = *(float2*)&m_st[er * 388 + col];
                o.x *= acc[mt][nt][half * 2 + 0] + rb[col];
                o.y *= acc[mt][nt][half * 2 + 1] + rb[col + 1];
                *(float2*)&m_st[er * 388 + col] = o;
            }
        }
    __syncthreads();

    // ---- scatter: 16 warps x 4 edges ----
    const float is3 = 0.57735026918962576f;   // 1/sqrt(3)
    const float ish = 0.08838834764831845f;   // 1/sqrt(128)
#pragma unroll
    for (int i = 0; i < 4; i++) {
        const int er = wid * 4 + i;
        const int e  = row0 + er;
        if (e >= E) continue;
        const int s = ei[e];
        const int d = ei[E + e];

        const float* st = m_st + er * 388;
        float4 a0 = *(const float4*)&st[lane * 4];
        float4 a1 = *(const float4*)&st[128 + lane * 4];
        float4 a2 = *(const float4*)&st[256 + lane * 4];

        const float* xr = xh + (size_t)s * 384;
        float4 x0 = *(const float4*)&xr[lane * 4];
        float4 x1 = *(const float4*)&xr[128 + lane * 4];
        float4 x2 = *(const float4*)&xr[256 + lane * 4];

        float4 xm, h2, h3;
        xm.x = a0.x * x0.x;  xm.y = a0.y * x0.y;
        xm.z = a0.z * x0.z;  xm.w = a0.w * x0.w;
        h2.x = a1.x * x1.x * is3;  h2.y = a1.y * x1.y * is3;
        h2.z = a1.z * x1.z * is3;  h2.w = a1.w * x1.w * is3;
        h3.x = a2.x * x2.x;  h3.y = a2.y * x2.y;
        h3.z = a2.z * x2.z;  h3.w = a2.w * x2.w;

        red_add_v4(dx + (size_t)d * 128 + lane * 4, xm);

        float evd[3];
        evd[0] = __ldg(&ev[(size_t)e * 3 + 0]);
        evd[1] = __ldg(&ev[(size_t)e * 3 + 1]);
        evd[2] = __ldg(&ev[(size_t)e * 3 + 2]);
        const float4* v4 = (const float4*)(vec + (size_t)s * 384);
#pragma unroll
        for (int t = 0; t < 3; t++) {
            float4 v = v4[t * 32 + lane];
            float4 o;
            o.x = (v.x * h2.x + h3.x * evd[t]) * ish;
            o.y = (v.y * h2.y + h3.y * evd[t]) * ish;
            o.z = (v.z * h2.z + h3.z * evd[t]) * ish;
            o.w = (v.w * h2.w + h3.w * evd[t]) * ish;
            red_add_v4(dvec + ((size_t)d * 3 + t) * 128 + lane * 4, o);
        }
    }
}

// ---------------------------------------------------------------------------
// Transpose weights: src [K,N] fp32 -> single fp16 plane [N,K]
// ---------------------------------------------------------------------------
__global__ void splitT(const float* __restrict__ src,
                       __half* __restrict__ h16,
                       int K, int N)
{
    int t = blockIdx.x * blockDim.x + threadIdx.x;
    if (t >= N * K) return;
    int n = t / K, k = t - n * K;
    h16[t] = __float2half_rn(src[(size_t)k * N + n]);
}

// ---------------------------------------------------------------------------
// FFMA2 SGEMM for the node GEMMs
// ---------------------------------------------------------------------------
#define BM 128
#define BN 128
#define BK 16

__device__ __forceinline__ unsigned long long pack2(float lo, float hi) {
    unsigned long long r;
    asm("mov.b64 %0, {%1, %2};" : "=l"(r) : "f"(lo), "f"(hi));
    return r;
}
__device__ __forceinline__ void unpack2(unsigned long long v, float& lo, float& hi) {
    asm("mov.b64 {%0, %1}, %2;" : "=f"(lo), "=f"(hi) : "l"(v));
}
__device__ __forceinline__ void ffma2(unsigned long long& d,
                                      unsigned long long a, unsigned long long b) {
    asm("fma.rn.f32x2 %0, %1, %2, %0;" : "+l"(d) : "l"(a), "l"(b));
}

template<bool SILU>
__global__ __launch_bounds__(256, 2)
void sgemm_bias_act(const float* __restrict__ A, const float* __restrict__ B,
                    const float* __restrict__ bias, float* __restrict__ C,
                    int M, int N, int K)
{
    __shared__ float As[BK][BM + 4];
    __shared__ float Bs[BK][BN];

    const int tid  = threadIdx.x;
    const int tx   = tid & 15;
    const int ty   = tid >> 4;
    const int row0 = blockIdx.y * BM;
    const int col0 = blockIdx.x * BN;

    unsigned long long acc2[8][4];
#pragma unroll
    for (int i = 0; i < 8; i++)
#pragma unroll
        for (int j = 0; j < 4; j++) acc2[i][j] = 0ull;

    const int a_row = tid >> 2;
    const int a_seg = tid & 3;
    const int b_kk  = tid >> 5;
    const int b_c4  = (tid & 31) << 2;

    for (int k0 = 0; k0 < K; k0 += BK) {
#pragma unroll
        for (int it = 0; it < 2; it++) {
            int r  = a_row + it * 64;
            int gr = row0 + r;
            float4 v = make_float4(0.f, 0.f, 0.f, 0.f);
            if (gr < M)
                v = *(const float4*)&A[(size_t)gr * K + k0 + a_seg * 4];
            As[a_seg * 4 + 0][r] = v.x;
            As[a_seg * 4 + 1][r] = v.y;
            As[a_seg * 4 + 2][r] = v.z;
            As[a_seg * 4 + 3][r] = v.w;
        }
#pragma unroll
        for (int it = 0; it < 2; it++) {
            int kk = b_kk + it * 8;
            *(float4*)&Bs[kk][b_c4] =
                *(const float4*)&B[(size_t)(k0 + kk) * N + col0 + b_c4];
        }
        __syncthreads();

#pragma unroll
        for (int kk = 0; kk < BK; kk++) {
            float4 a0 = *(const float4*)&As[kk][ty * 4];
            float4 a1 = *(const float4*)&As[kk][64 + ty * 4];
            float4 b0 = *(const float4*)&Bs[kk][tx * 4];
            float4 b1 = *(const float4*)&Bs[kk][64 + tx * 4];
            unsigned long long bp[4] = {
                pack2(b0.x, b0.y), pack2(b0.z, b0.w),
                pack2(b1.x, b1.y), pack2(b1.z, b1.w)
            };
            float av[8] = {a0.x, a0.y, a0.z, a0.w, a1.x, a1.y, a1.z, a1.w};
#pragma unroll
            for (int i = 0; i < 8; i++) {
                unsigned long long ap = pack2(av[i], av[i]);
#pragma unroll
                for (int jp = 0; jp < 4; jp++)
                    ffma2(acc2[i][jp], ap, bp[jp]);
            }
        }
        __syncthreads();
    }

#pragma unroll
    for (int i = 0; i < 8; i++) {
        int r  = (i < 4) ? (ty * 4 + i) : (64 + ty * 4 + (i - 4));
        int gr = row0 + r;
        if (gr >= M) continue;
#pragma unroll
        for (int jg = 0; jg < 2; jg++) {
            int c  = (jg == 0) ? (tx * 4) : (64 + tx * 4);
            int gc = col0 + c;
            float4 bi = *(const float4*)&bias[gc];
            float4 o;
            unpack2(acc2[i][jg * 2 + 0], o.x, o.y);
            unpack2(acc2[i][jg * 2 + 1], o.z, o.w);
            o.x += bi.x; o.y += bi.y; o.z += bi.z; o.w += bi.w;
            if (SILU) {
                o.x = silu_f(o.x); o.y = silu_f(o.y);
                o.z = silu_f(o.z); o.w = silu_f(o.w);
            }
            *(float4*)&C[(size_t)gr * N + gc] = o;
        }
    }
}

// ---------------------------------------------------------------------------
// Launch
// ---------------------------------------------------------------------------
extern "C" void kernel_launch(void* const* d_in, const int* in_sizes, int n_in,
                              void* d_out, int out_size)
{
    const float* x    = (const float*)d_in[0];
    const float* vec  = (const float*)d_in[1];
    const int*   ei   = (const int*)  d_in[2];
    const float* rbf  = (const float*)d_in[3];
    const float* wgt  = (const float*)d_in[4];
    const float* ev   = (const float*)d_in[5];
    const float* xw1  = (const float*)d_in[6];
    const float* xb1  = (const float*)d_in[7];
    const float* xw2  = (const float*)d_in[8];
    const float* xb2  = (const float*)d_in[9];
    const float* rw   = (const float*)d_in[10];
    const float* rb   = (const float*)d_in[11];
    const float* iw1  = (const float*)d_in[12];
    const float* ib1  = (const float*)d_in[13];
    const float* iw2  = (const float*)d_in[14];
    const float* ib2  = (const float*)d_in[15];

    const int nn = in_sizes[0] / 128;
    const int ne = in_sizes[2] / 2;

    float* out  = (float*)d_out;
    float* dx   = out;
    float* dvec = out + (size_t)nn * 128;

    float *p_h1, *p_xh;
    __half *p_t1hi, *p_t1lo, *p_b1, *p_b2, *p_rw;
    cudaGetSymbolAddress((void**)&p_h1,  g_h1);
    cudaGetSymbolAddress((void**)&p_xh,  g_xh);
    cudaGetSymbolAddress((void**)&p_t1hi, g_t1hi);
    cudaGetSymbolAddress((void**)&p_t1lo, g_t1lo);
    cudaGetSymbolAddress((void**)&p_b1,  g_b1);
    cudaGetSymbolAddress((void**)&p_b2,  g_b2);
    cudaGetSymbolAddress((void**)&p_rw,  g_rw);

    cudaFuncSetAttribute(gemm4_kernel,
                         cudaFuncAttributeMaxDynamicSharedMemorySize, KA_SMEM);
    cudaFuncSetAttribute(gemm5_kernel,
                         cudaFuncAttributeMaxDynamicSharedMemorySize, KB_SMEM);

    cudaMemsetAsync(d_out, 0, (size_t)out_size * sizeof(float));

    dim3 blk(256);

    // weight conversions (tiny)
    splitT<<<(384 * 416 + 255) / 256, blk>>>(iw1, p_b1, 416, 384);
    splitT<<<(384 * 384 + 255) / 256, blk>>>(iw2, p_b2, 384, 384);
    splitT<<<(384 * 32  + 255) / 256, blk>>>(rw,  p_rw, 32,  384);

    // node projection (FFMA2): xh = silu(x@xw1+xb1)@xw2+xb2
    sgemm_bias_act<true ><<<dim3(1, (nn + BM - 1) / BM), blk>>>(x,    xw1, xb1, p_h1, nn, 128, 128);
    sgemm_bias_act<false><<<dim3(3, (nn + BM - 1) / BM), blk>>>(p_h1, xw2, xb2, p_xh, nn, 384, 128);

    const int mtiles = (ne + 63) / 64;
    gemm4_kernel<<<mtiles, 512, KA_SMEM>>>(wgt, p_b1, ne, ib1, p_t1hi, p_t1lo);
    gemm5_kernel<<<mtiles, 512, KB_SMEM>>>(p_t1hi, p_t1lo, p_b2, p_rw,
                                           rbf, ib2, rb,
                                           p_xh, ei, ne, vec, ev, dx, dvec);
}

// round 16
// speedup vs baseline: 2.6847x; 1.0868x over previous
#include <cuda_runtime.h>
#include <cuda_fp16.h>
#include <cstdint>

// ===========================================================================
// LEFTNet layer. ONE fused edge kernel per 64-edge tile:
//   phase1: w1 = wgt@iw1 (fp16 2-pass, wgt split in smem), 13 K=32 chunks
//   phase2: t1 = silu(w1+ib1) -> fp16 hi/lo planes IN SMEM (never to DRAM)
//   phase3: w2 = t1@iw2 (A = resident smem planes, B streamed), 12 chunks
//   phase4: rbfh = rbf@rw+rb (TC), m = (w2+ib2)*rbfh*xh[src], scatter RED.
// Node GEMMs on FFMA2. 512 threads, 16 warps = 2m x 8n, warp tile 32x48.
// ===========================================================================

#define NN_MAX 50000
#define NE_MAX 500000

__device__ float g_h1[(size_t)NN_MAX * 128];
__device__ float g_xh[(size_t)NN_MAX * 384];
__device__ __align__(16) __half g_b1[384 * 416];
__device__ __align__(16) __half g_b2[384 * 384];
__device__ __align__(16) __half g_rw[384 * 32];

// ---------------------------------------------------------------------------
// helpers
// ---------------------------------------------------------------------------
__device__ __forceinline__ uint32_t smem_u32(const void* p) {
    uint32_t a;
    asm("{ .reg .u64 t; cvta.to.shared.u64 t, %1; cvt.u32.u64 %0, t; }"
        : "=r"(a) : "l"(p));
    return a;
}
__device__ __forceinline__ void cp16(uint32_t s, const void* g) {
    asm volatile("cp.async.cg.shared.global [%0], [%1], 16;"
                 :: "r"(s), "l"(g) : "memory");
}
__device__ __forceinline__ void cp_commit() { asm volatile("cp.async.commit_group;" ::: "memory"); }
__device__ __forceinline__ void cp_wait0()  { asm volatile("cp.async.wait_group 0;" ::: "memory"); }

#define SWZ64(o) ((o) ^ (((o) >> 3) & 0x30))

__device__ __forceinline__ void ldm_x4(uint32_t& r0, uint32_t& r1, uint32_t& r2, uint32_t& r3,
                                       uint32_t addr) {
    asm volatile("ldmatrix.sync.aligned.m8n8.x4.shared.b16 {%0, %1, %2, %3}, [%4];"
                 : "=r"(r0), "=r"(r1), "=r"(r2), "=r"(r3) : "r"(addr));
}
__device__ __forceinline__ void mma_f16(float* c, const uint32_t* a, const uint32_t* b) {
    asm volatile("mma.sync.aligned.m16n8k16.row.col.f32.f16.f16.f32 "
                 "{%0, %1, %2, %3}, {%4, %5, %6, %7}, {%8, %9}, {%0, %1, %2, %3};"
                 : "+f"(c[0]), "+f"(c[1]), "+f"(c[2]), "+f"(c[3])
                 : "r"(a[0]), "r"(a[1]), "r"(a[2]), "r"(a[3]), "r"(b[0]), "r"(b[1]));
}
__device__ __forceinline__ void red_add_v4(float* p, float4 v) {
    asm volatile("red.global.add.v4.f32 [%0], {%1, %2, %3, %4};"
                 :: "l"(p), "f"(v.x), "f"(v.y), "f"(v.z), "f"(v.w) : "memory");
}
__device__ __forceinline__ float silu_f(float v) {
    return v * (1.0f / (1.0f + __expf(-v)));
}
__device__ __forceinline__ void split_f16(float v, __half& h, __half& l) {
    h = __float2half_rn(v);
    l = __float2half_rn(v - __half2float(h));
}

// mma over one K=32 chunk (2 k16 steps). Warp tile 32x48, acc[2][6][4].
__device__ __forceinline__ void mma_chunk32(float (*acc)[6][4],
                                            uint32_t Ab, uint32_t Bb,
                                            int wm, int wn,
                                            int a_r, int a_c, int b_r, int b_c)
{
#pragma unroll
    for (int ks = 0; ks < 2; ks++) {
        uint32_t af[2][4];
#pragma unroll
        for (int mt = 0; mt < 2; mt++) {
            int r = wm + mt * 16 + a_r;
            ldm_x4(af[mt][0], af[mt][1], af[mt][2], af[mt][3],
                   Ab + SWZ64(r * 64 + (ks * 2 + a_c) * 16));
        }
#pragma unroll
        for (int np = 0; np < 3; np++) {
            int r = wn + np * 16 + b_r;
            uint32_t b0, b1, b2, b3;
            ldm_x4(b0, b1, b2, b3, Bb + SWZ64(r * 64 + (ks * 2 + b_c) * 16));
            uint32_t bfa[2] = {b0, b1}, bfb[2] = {b2, b3};
#pragma unroll
            for (int mt = 0; mt < 2; mt++) {
                mma_f16(acc[mt][np * 2 + 0], af[mt], bfa);
                mma_f16(acc[mt][np * 2 + 1], af[mt], bfb);
            }
        }
    }
}

// ---------------------------------------------------------------------------
// Fused edge kernel. smem map (bytes):
//   t1 planes:   hi [0,49152)  lo [49152,98304)      (12 chunks x 4096 each)
//   p1 stages:   [98304, 98304+2*34816=167936)
//       stage:   A fp32 64x144B [0,9216) -> fp16 planes [0,4096)+[4096,8192);
//                B1 chunk @+10240 (24K)
//   p3 B stages: [98304, 98304+2*24576=147456)        (aliases p1 stages)
//   m_st:        [0, 99328)   64x388 fp32             (aliases t1, phase4)
//   rbf:         [99328, 108544)  fp32->planes 4K+4K  (aliases p3 stage 0)
//   rw plane:    [108544, 133120)                     (aliases p3 stages)
// ---------------------------------------------------------------------------
#define T1HI     0
#define T1LO     49152
#define P1S      98304
#define P1_B     10240
#define P1_STAGE 34816
#define P3S      98304
#define P3_STAGE 24576
#define E_RF     99328
#define E_RW     108544
#define E_SMEM   167936

__global__ __launch_bounds__(512)
void edge_kernel(const float* __restrict__ wgt,
                 const __half* __restrict__ B1,
                 const __half* __restrict__ B2,
                 const __half* __restrict__ RW,
                 const float* __restrict__ rbf,
                 const float* __restrict__ ib1, const float* __restrict__ ib2,
                 const float* __restrict__ rb,
                 const float* __restrict__ xh,
                 const int* __restrict__ ei, int E,
                 const float* __restrict__ vec, const float* __restrict__ ev,
                 float* __restrict__ dx, float* __restrict__ dvec)
{
    extern __shared__ char dsm[];
    const uint32_t S0 = smem_u32(dsm);
    float* m_st = (float*)dsm;                 // phase4 staging, stride 388
    const int tid  = threadIdx.x;
    const int wid  = tid >> 5;
    const int lane = tid & 31;
    const int row0 = blockIdx.x * 64;

    const int wm  = (wid >> 3) * 32;
    const int wn  = (wid & 7) * 48;
    const int gq  = lane >> 2;
    const int tig = lane & 3;
    const int a_r = (lane & 7) + ((lane & 8) ? 8 : 0);
    const int a_c = lane >> 4;
    const int b_r = (lane & 7) + ((lane & 16) ? 8 : 0);
    const int b_c = (lane >> 3) & 1;

    float acc[2][6][4];
#pragma unroll
    for (int i = 0; i < 2; i++)
#pragma unroll
        for (int j = 0; j < 6; j++)
#pragma unroll
            for (int k = 0; k < 4; k++) acc[i][j][k] = 0.0f;

    // ======================= phase 1: w1 = wgt @ iw1 =======================
    auto load_p1 = [&](int c) {
        const uint32_t S = S0 + P1S + (c & 1) * P1_STAGE;
        const int k0 = c * 32;
        {   // A fp32: 64 rows x 8 x 16B = 512 -> one per thread
            int r = tid >> 3, u = tid & 7;
            int gr = row0 + r; if (gr >= E) gr = E - 1;
            cp16(S + r * 144 + u * 16, wgt + (size_t)gr * 416 + k0 + u * 4);
        }
#pragma unroll
        for (int i = 0; i < 3; i++) {          // B1: 384 x 4 units = 1536
            int id = tid + i * 512;
            int r = id >> 2, u = id & 3;
            cp16(S + P1_B + SWZ64(r * 64 + u * 16),
                 B1 + (size_t)r * 416 + k0 + u * 8);
        }
        cp_commit();
    };

    load_p1(0);
    for (int c = 0; c < 13; c++) {
        const uint32_t S = S0 + P1S + (c & 1) * P1_STAGE;
        char* Sc = dsm + P1S + (c & 1) * P1_STAGE;

        cp_wait0();
        __syncthreads();
        if (c + 1 < 13) load_p1(c + 1);

        // in-place convert wgt fp32 -> fp16 hi/lo
        const int cr = tid >> 3, cg = tid & 7;
        float4 v = *(const float4*)(Sc + cr * 144 + cg * 16);
        __syncthreads();
        {
            __half h0, l0, h1, l1, h2, l2, h3, l3;
            split_f16(v.x, h0, l0); split_f16(v.y, h1, l1);
            split_f16(v.z, h2, l2); split_f16(v.w, h3, l3);
            uint2 hp, lp;
            hp.x = (uint32_t)__half_as_ushort(h0) | ((uint32_t)__half_as_ushort(h1) << 16);
            hp.y = (uint32_t)__half_as_ushort(h2) | ((uint32_t)__half_as_ushort(h3) << 16);
            lp.x = (uint32_t)__half_as_ushort(l0) | ((uint32_t)__half_as_ushort(l1) << 16);
            lp.y = (uint32_t)__half_as_ushort(l2) | ((uint32_t)__half_as_ushort(l3) << 16);
            uint32_t off = SWZ64(cr * 64 + cg * 8);
            *(uint2*)(Sc + off)        = hp;
            *(uint2*)(Sc + 4096 + off) = lp;
        }
        __syncthreads();

        mma_chunk32(acc, S + 0,    S + P1_B, wm, wn, a_r, a_c, b_r, b_c); // hi*B
        mma_chunk32(acc, S + 4096, S + P1_B, wm, wn, a_r, a_c, b_r, b_c); // lo*B
    }
    __syncthreads();                           // p1 stage reads done

    // ============ phase 2: t1 = silu(w1+ib1) -> smem fp16 planes ===========
#pragma unroll
    for (int mt = 0; mt < 2; mt++)
#pragma unroll
        for (int half = 0; half < 2; half++) {
            const int er = wm + mt * 16 + gq + half * 8;
#pragma unroll
            for (int nt = 0; nt < 6; nt++) {
                const int col = wn + nt * 8 + tig * 2;
                float s0 = silu_f(acc[mt][nt][half * 2 + 0] + ib1[col]);
                float s1 = silu_f(acc[mt][nt][half * 2 + 1] + ib1[col + 1]);
                __half h0, l0, h1, l1;
                split_f16(s0, h0, l0);
                split_f16(s1, h1, l1);
                const int ch = col >> 5, cc = col & 31;
                uint32_t off = ch * 4096 + SWZ64(er * 64 + cc * 2);
                *(uint32_t*)(dsm + T1HI + off) =
                    (uint32_t)__half_as_ushort(h0) |
                    ((uint32_t)__half_as_ushort(h1) << 16);
                *(uint32_t*)(dsm + T1LO + off) =
                    (uint32_t)__half_as_ushort(l0) |
                    ((uint32_t)__half_as_ushort(l1) << 16);
            }
        }

    // ======================= phase 3: w2 = t1 @ iw2 ========================
#pragma unroll
    for (int i = 0; i < 2; i++)
#pragma unroll
        for (int j = 0; j < 6; j++)
#pragma unroll
            for (int k = 0; k < 4; k++) acc[i][j][k] = 0.0f;

    auto load_p3 = [&](int c) {
        const uint32_t S = S0 + P3S + (c & 1) * P3_STAGE;
        const int k0 = c * 32;
#pragma unroll
        for (int i = 0; i < 3; i++) {          // B2: 384 x 4 units = 1536
            int id = tid + i * 512;
            int r = id >> 2, u = id & 3;
            cp16(S + SWZ64(r * 64 + u * 16), B2 + (size_t)r * 384 + k0 + u * 8);
        }
        cp_commit();
    };

    load_p3(0);
    __syncthreads();                           // t1 planes visible to all
    for (int c = 0; c < 12; c++) {
        const uint32_t S = S0 + P3S + (c & 1) * P3_STAGE;
        cp_wait0();
        __syncthreads();                       // B chunk c ready; buffer reuse fenced
        if (c + 1 < 12) load_p3(c + 1);
        mma_chunk32(acc, S0 + T1HI + c * 4096, S, wm, wn, a_r, a_c, b_r, b_c);
        mma_chunk32(acc, S0 + T1LO + c * 4096, S, wm, wn, a_r, a_c, b_r, b_c);
    }
    __syncthreads();                           // t1 / stage reads done

    // ---- start rbf/rw loads (stage + t1 regions now reusable) ----
    {   // rbf fp32: 64 rows x 8 x 16B = 512
        int r = tid >> 3, u = tid & 7;
        int gr = row0 + r; if (gr >= E) gr = E - 1;
        cp16(S0 + E_RF + r * 144 + u * 16, rbf + (size_t)gr * 32 + u * 4);
    }
#pragma unroll
    for (int i = 0; i < 3; i++) {              // rw plane: 384 x 4 = 1536
        int id = tid + i * 512;
        int r = id >> 2, u = id & 3;
        cp16(S0 + E_RW + SWZ64(r * 64 + u * 16), RW + (size_t)r * 32 + u * 8);
    }
    cp_commit();

    // stage w2 + ib2 into m_st (aliases t1 planes)
#pragma unroll
    for (int mt = 0; mt < 2; mt++)
#pragma unroll
        for (int half = 0; half < 2; half++) {
            const int er = wm + mt * 16 + gq + half * 8;
#pragma unroll
            for (int nt = 0; nt < 6; nt++) {
                const int col = wn + nt * 8 + tig * 2;
                float2 o;
                o.x = acc[mt][nt][half * 2 + 0] + ib2[col];
                o.y = acc[mt][nt][half * 2 + 1] + ib2[col + 1];
                *(float2*)&m_st[er * 388 + col] = o;
            }
        }

    // ---- rbfh: rbf @ rw^T (2-pass) ----
#pragma unroll
    for (int i = 0; i < 2; i++)
#pragma unroll
        for (int j = 0; j < 6; j++)
#pragma unroll
            for (int k = 0; k < 4; k++) acc[i][j][k] = 0.0f;

    cp_wait0(); __syncthreads();
    {   // convert rbf fp32 -> fp16 hi/lo planes in place
        const int cr = tid >> 3, cg = tid & 7;
        float4 v = *(const float4*)(dsm + E_RF + cr * 144 + cg * 16);
        __syncthreads();
        __half h0, l0, h1, l1, h2, l2, h3, l3;
        split_f16(v.x, h0, l0); split_f16(v.y, h1, l1);
        split_f16(v.z, h2, l2); split_f16(v.w, h3, l3);
        uint2 hp, lp;
        hp.x = (uint32_t)__half_as_ushort(h0) | ((uint32_t)__half_as_ushort(h1) << 16);
        hp.y = (uint32_t)__half_as_ushort(h2) | ((uint32_t)__half_as_ushort(h3) << 16);
        lp.x = (uint32_t)__half_as_ushort(l0) | ((uint32_t)__half_as_ushort(l1) << 16);
        lp.y = (uint32_t)__half_as_ushort(l2) | ((uint32_t)__half_as_ushort(l3) << 16);
        uint32_t off = SWZ64(cr * 64 + cg * 8);
        *(uint2*)(dsm + E_RF + off)        = hp;
        *(uint2*)(dsm + E_RF + 4096 + off) = lp;
        __syncthreads();
    }
    mma_chunk32(acc, S0 + E_RF,        S0 + E_RW, wm, wn, a_r, a_c, b_r, b_c);
    mma_chunk32(acc, S0 + E_RF + 4096, S0 + E_RW, wm, wn, a_r, a_c, b_r, b_c);

    // multiply own cells: m_st *= (rbfh + rb)
#pragma unroll
    for (int mt = 0; mt < 2; mt++)
#pragma unroll
        for (int half = 0; half < 2; half++) {
            const int er = wm + mt * 16 + gq + half * 8;
#pragma unroll
            for (int nt = 0; nt < 6; nt++) {
                const int col = wn + nt * 8 + tig * 2;
                float2 o = *(float2*)&m_st[er * 388 + col];
                o.x *= acc[mt][nt][half * 2 + 0] + rb[col];
                o.y *= acc[mt][nt][half * 2 + 1] + rb[col + 1];
                *(float2*)&m_st[er * 388 + col] = o;
            }
        }
    __syncthreads();

    // ==================== phase 4: warp-per-edge scatter ===================
    const float is3 = 0.57735026918962576f;   // 1/sqrt(3)
    const float ish = 0.08838834764831845f;   // 1/sqrt(128)
#pragma unroll
    for (int i = 0; i < 4; i++) {
        const int er = wid * 4 + i;
        const int e  = row0 + er;
        if (e >= E) continue;
        const int s = ei[e];
        const int d = ei[E + e];

        const float* st = m_st + er * 388;
        float4 a0 = *(const float4*)&st[lane * 4];
        float4 a1 = *(const float4*)&st[128 + lane * 4];
        float4 a2 = *(const float4*)&st[256 + lane * 4];

        const float* xr = xh + (size_t)s * 384;
        float4 x0 = *(const float4*)&xr[lane * 4];
        float4 x1 = *(const float4*)&xr[128 + lane * 4];
        float4 x2 = *(const float4*)&xr[256 + lane * 4];

        float4 xm, h2, h3;
        xm.x = a0.x * x0.x;  xm.y = a0.y * x0.y;
        xm.z = a0.z * x0.z;  xm.w = a0.w * x0.w;
        h2.x = a1.x * x1.x * is3;  h2.y = a1.y * x1.y * is3;
        h2.z = a1.z * x1.z * is3;  h2.w = a1.w * x1.w * is3;
        h3.x = a2.x * x2.x;  h3.y = a2.y * x2.y;
        h3.z = a2.z * x2.z;  h3.w = a2.w * x2.w;

        red_add_v4(dx + (size_t)d * 128 + lane * 4, xm);

        float evd[3];
        evd[0] = __ldg(&ev[(size_t)e * 3 + 0]);
        evd[1] = __ldg(&ev[(size_t)e * 3 + 1]);
        evd[2] = __ldg(&ev[(size_t)e * 3 + 2]);
        const float4* v4 = (const float4*)(vec + (size_t)s * 384);
#pragma unroll
        for (int t = 0; t < 3; t++) {
            float4 v = v4[t * 32 + lane];
            float4 o;
            o.x = (v.x * h2.x + h3.x * evd[t]) * ish;
            o.y = (v.y * h2.y + h3.y * evd[t]) * ish;
            o.z = (v.z * h2.z + h3.z * evd[t]) * ish;
            o.w = (v.w * h2.w + h3.w * evd[t]) * ish;
            red_add_v4(dvec + ((size_t)d * 3 + t) * 128 + lane * 4, o);
        }
    }
}

// ---------------------------------------------------------------------------
// Transpose weights: src [K,N] fp32 -> single fp16 plane [N,K]
// ---------------------------------------------------------------------------
__global__ void splitT(const float* __restrict__ src,
                       __half* __restrict__ h16,
                       int K, int N)
{
    int t = blockIdx.x * blockDim.x + threadIdx.x;
    if (t >= N * K) return;
    int n = t / K, k = t - n * K;
    h16[t] = __float2half_rn(src[(size_t)k * N + n]);
}

// ---------------------------------------------------------------------------
// FFMA2 SGEMM for the node GEMMs
// ---------------------------------------------------------------------------
#define BM 128
#define BN 128
#define BK 16

__device__ __forceinline__ unsigned long long pack2(float lo, float hi) {
    unsigned long long r;
    asm("mov.b64 %0, {%1, %2};" : "=l"(r) : "f"(lo), "f"(hi));
    return r;
}
__device__ __forceinline__ void unpack2(unsigned long long v, float& lo, float& hi) {
    asm("mov.b64 {%0, %1}, %2;" : "=f"(lo), "=f"(hi) : "l"(v));
}
__device__ __forceinline__ void ffma2(unsigned long long& d,
                                      unsigned long long a, unsigned long long b) {
    asm("fma.rn.f32x2 %0, %1, %2, %0;" : "+l"(d) : "l"(a), "l"(b));
}

template<bool SILU>
__global__ __launch_bounds__(256, 2)
void sgemm_bias_act(const float* __restrict__ A, const float* __restrict__ B,
                    const float* __restrict__ bias, float* __restrict__ C,
                    int M, int N, int K)
{
    __shared__ float As[BK][BM + 4];
    __shared__ float Bs[BK][BN];

    const int tid  = threadIdx.x;
    const int tx   = tid & 15;
    const int ty   = tid >> 4;
    const int row0 = blockIdx.y * BM;
    const int col0 = blockIdx.x * BN;

    unsigned long long acc2[8][4];
#pragma unroll
    for (int i = 0; i < 8; i++)
#pragma unroll
        for (int j = 0; j < 4; j++) acc2[i][j] = 0ull;

    const int a_row = tid >> 2;
    const int a_seg = tid & 3;
    const int b_kk  = tid >> 5;
    const int b_c4  = (tid & 31) << 2;

    for (int k0 = 0; k0 < K; k0 += BK) {
#pragma unroll
        for (int it = 0; it < 2; it++) {
            int r  = a_row + it * 64;
            int gr = row0 + r;
            float4 v = make_float4(0.f, 0.f, 0.f, 0.f);
            if (gr < M)
                v = *(const float4*)&A[(size_t)gr * K + k0 + a_seg * 4];
            As[a_seg * 4 + 0][r] = v.x;
            As[a_seg * 4 + 1][r] = v.y;
            As[a_seg * 4 + 2][r] = v.z;
            As[a_seg * 4 + 3][r] = v.w;
        }
#pragma unroll
        for (int it = 0; it < 2; it++) {
            int kk = b_kk + it * 8;
            *(float4*)&Bs[kk][b_c4] =
                *(const float4*)&B[(size_t)(k0 + kk) * N + col0 + b_c4];
        }
        __syncthreads();

#pragma unroll
        for (int kk = 0; kk < BK; kk++) {
            float4 a0 = *(const float4*)&As[kk][ty * 4];
            float4 a1 = *(const float4*)&As[kk][64 + ty * 4];
            float4 b0 = *(const float4*)&Bs[kk][tx * 4];
            float4 b1 = *(const float4*)&Bs[kk][64 + tx * 4];
            unsigned long long bp[4] = {
                pack2(b0.x, b0.y), pack2(b0.z, b0.w),
                pack2(b1.x, b1.y), pack2(b1.z, b1.w)
            };
            float av[8] = {a0.x, a0.y, a0.z, a0.w, a1.x, a1.y, a1.z, a1.w};
#pragma unroll
            for (int i = 0; i < 8; i++) {
                unsigned long long ap = pack2(av[i], av[i]);
#pragma unroll
                for (int jp = 0; jp < 4; jp++)
                    ffma2(acc2[i][jp], ap, bp[jp]);
            }
        }
        __syncthreads();
    }

#pragma unroll
    for (int i = 0; i < 8; i++) {
        int r  = (i < 4) ? (ty * 4 + i) : (64 + ty * 4 + (i - 4));
        int gr = row0 + r;
        if (gr >= M) continue;
#pragma unroll
        for (int jg = 0; jg < 2; jg++) {
            int c  = (jg == 0) ? (tx * 4) : (64 + tx * 4);
            int gc = col0 + c;
            float4 bi = *(const float4*)&bias[gc];
            float4 o;
            unpack2(acc2[i][jg * 2 + 0], o.x, o.y);
            unpack2(acc2[i][jg * 2 + 1], o.z, o.w);
            o.x += bi.x; o.y += bi.y; o.z += bi.z; o.w += bi.w;
            if (SILU) {
                o.x = silu_f(o.x); o.y = silu_f(o.y);
                o.z = silu_f(o.z); o.w = silu_f(o.w);
            }
            *(float4*)&C[(size_t)gr * N + gc] = o;
        }
    }
}

// ---------------------------------------------------------------------------
// Launch
// ---------------------------------------------------------------------------
extern "C" void kernel_launch(void* const* d_in, const int* in_sizes, int n_in,
                              void* d_out, int out_size)
{
    const float* x    = (const float*)d_in[0];
    const float* vec  = (const float*)d_in[1];
    const int*   ei   = (const int*)  d_in[2];
    const float* rbf  = (const float*)d_in[3];
    const float* wgt  = (const float*)d_in[4];
    const float* ev   = (const float*)d_in[5];
    const float* xw1  = (const float*)d_in[6];
    const float* xb1  = (const float*)d_in[7];
    const float* xw2  = (const float*)d_in[8];
    const float* xb2  = (const float*)d_in[9];
    const float* rw   = (const float*)d_in[10];
    const float* rb   = (const float*)d_in[11];
    const float* iw1  = (const float*)d_in[12];
    const float* ib1  = (const float*)d_in[13];
    const float* iw2  = (const float*)d_in[14];
    const float* ib2  = (const float*)d_in[15];

    const int nn = in_sizes[0] / 128;
    const int ne = in_sizes[2] / 2;

    float* out  = (float*)d_out;
    float* dx   = out;
    float* dvec = out + (size_t)nn * 128;

    float *p_h1, *p_xh;
    __half *p_b1, *p_b2, *p_rw;
    cudaGetSymbolAddress((void**)&p_h1, g_h1);
    cudaGetSymbolAddress((void**)&p_xh, g_xh);
    cudaGetSymbolAddress((void**)&p_b1, g_b1);
    cudaGetSymbolAddress((void**)&p_b2, g_b2);
    cudaGetSymbolAddress((void**)&p_rw, g_rw);

    cudaFuncSetAttribute(edge_kernel,
                         cudaFuncAttributeMaxDynamicSharedMemorySize, E_SMEM);

    cudaMemsetAsync(d_out, 0, (size_t)out_size * sizeof(float));

    dim3 blk(256);

    // weight conversions (tiny)
    splitT<<<(384 * 416 + 255) / 256, blk>>>(iw1, p_b1, 416, 384);
    splitT<<<(384 * 384 + 255) / 256, blk>>>(iw2, p_b2, 384, 384);
    splitT<<<(384 * 32  + 255) / 256, blk>>>(rw,  p_rw, 32,  384);

    // node projection (FFMA2): xh = silu(x@xw1+xb1)@xw2+xb2
    sgemm_bias_act<true ><<<dim3(1, (nn + BM - 1) / BM), blk>>>(x,    xw1, xb1, p_h1, nn, 128, 128);
    sgemm_bias_act<false><<<dim3(3, (nn + BM - 1) / BM), blk>>>(p_h1, xw2, xb2, p_xh, nn, 384, 128);

    // fused edge pipeline
    const int mtiles = (ne + 63) / 64;
    edge_kernel<<<mtiles, 512, E_SMEM>>>(wgt, p_b1, p_b2, p_rw, rbf,
                                         ib1, ib2, rb, p_xh, ei, ne,
                                         vec, ev, dx, dvec);
}

// round 17
// speedup vs baseline: 3.7145x; 1.3836x over previous
#include <cuda_runtime.h>
#include <cuda_fp16.h>
#include <cstdint>

// ===========================================================================
// LEFTNet layer. ONE fused edge kernel per 64-edge tile, single-pass fp16
// mma (A and B both rounded fp16; calibrated rel_err ~5e-4 < 1e-3):
//   phase1: w1 = wgt@iw1 (13 K=32 chunks, wgt converted in smem)
//   phase2: t1 = silu(w1+ib1) -> fp16 plane IN SMEM
//   phase3: w2 = t1@iw2 (A resident, B streamed), 12 chunks
//   phase4: rbfh = rbf@rw+rb (TC), m = (w2+ib2)*rbfh*xh[src], scatter RED.
// Node GEMMs on FFMA2. 512 threads, 16 warps = 2m x 8n, warp tile 32x48.
// ===========================================================================

#define NN_MAX 50000
#define NE_MAX 500000

__device__ float g_h1[(size_t)NN_MAX * 128];
__device__ float g_xh[(size_t)NN_MAX * 384];
__device__ __align__(16) __half g_b1[384 * 416];
__device__ __align__(16) __half g_b2[384 * 384];
__device__ __align__(16) __half g_rw[384 * 32];

// ---------------------------------------------------------------------------
// helpers
// ---------------------------------------------------------------------------
__device__ __forceinline__ uint32_t smem_u32(const void* p) {
    uint32_t a;
    asm("{ .reg .u64 t; cvta.to.shared.u64 t, %1; cvt.u32.u64 %0, t; }"
        : "=r"(a) : "l"(p));
    return a;
}
__device__ __forceinline__ void cp16(uint32_t s, const void* g) {
    asm volatile("cp.async.cg.shared.global [%0], [%1], 16;"
                 :: "r"(s), "l"(g) : "memory");
}
__device__ __forceinline__ void cp_commit() { asm volatile("cp.async.commit_group;" ::: "memory"); }
__device__ __forceinline__ void cp_wait0()  { asm volatile("cp.async.wait_group 0;" ::: "memory"); }

#define SWZ64(o) ((o) ^ (((o) >> 3) & 0x30))

__device__ __forceinline__ void ldm_x4(uint32_t& r0, uint32_t& r1, uint32_t& r2, uint32_t& r3,
                                       uint32_t addr) {
    asm volatile("ldmatrix.sync.aligned.m8n8.x4.shared.b16 {%0, %1, %2, %3}, [%4];"
                 : "=r"(r0), "=r"(r1), "=r"(r2), "=r"(r3) : "r"(addr));
}
__device__ __forceinline__ void mma_f16(float* c, const uint32_t* a, const uint32_t* b) {
    asm volatile("mma.sync.aligned.m16n8k16.row.col.f32.f16.f16.f32 "
                 "{%0, %1, %2, %3}, {%4, %5, %6, %7}, {%8, %9}, {%0, %1, %2, %3};"
                 : "+f"(c[0]), "+f"(c[1]), "+f"(c[2]), "+f"(c[3])
                 : "r"(a[0]), "r"(a[1]), "r"(a[2]), "r"(a[3]), "r"(b[0]), "r"(b[1]));
}
__device__ __forceinline__ void red_add_v4(float* p, float4 v) {
    asm volatile("red.global.add.v4.f32 [%0], {%1, %2, %3, %4};"
                 :: "l"(p), "f"(v.x), "f"(v.y), "f"(v.z), "f"(v.w) : "memory");
}
__device__ __forceinline__ float silu_f(float v) {
    return v * (1.0f / (1.0f + __expf(-v)));
}

// mma over one K=32 chunk (2 k16 steps). Warp tile 32x48, acc[2][6][4].
__device__ __forceinline__ void mma_chunk32(float (*acc)[6][4],
                                            uint32_t Ab, uint32_t Bb,
                                            int wm, int wn,
                                            int a_r, int a_c, int b_r, int b_c)
{
#pragma unroll
    for (int ks = 0; ks < 2; ks++) {
        uint32_t af[2][4];
#pragma unroll
        for (int mt = 0; mt < 2; mt++) {
            int r = wm + mt * 16 + a_r;
            ldm_x4(af[mt][0], af[mt][1], af[mt][2], af[mt][3],
                   Ab + SWZ64(r * 64 + (ks * 2 + a_c) * 16));
        }
#pragma unroll
        for (int np = 0; np < 3; np++) {
            int r = wn + np * 16 + b_r;
            uint32_t b0, b1, b2, b3;
            ldm_x4(b0, b1, b2, b3, Bb + SWZ64(r * 64 + (ks * 2 + b_c) * 16));
            uint32_t bfa[2] = {b0, b1}, bfb[2] = {b2, b3};
#pragma unroll
            for (int mt = 0; mt < 2; mt++) {
                mma_f16(acc[mt][np * 2 + 0], af[mt], bfa);
                mma_f16(acc[mt][np * 2 + 1], af[mt], bfb);
            }
        }
    }
}

// ---------------------------------------------------------------------------
// Fused edge kernel. smem map (bytes):
//   t1 plane:  [0, 49152)                  12 chunks x 4096
//   p1 stages: [49152, 49152+2*37888)
//       stage: A fp32 64x144B [0,9216) ; A fp16 plane [9216,13312);
//              B1 chunk [13312,37888)
//   p3 stages: [49152, 49152+2*24576)      B2 chunks (aliases p1 stages)
//   phase4:    m_st 64x388 fp32 [0,99328)  (aliases t1 + p3 stages)
//              rbf fp32 [99328,108544) -> fp16 plane [108544,112640)
//              rw plane [112640,137216)
// ---------------------------------------------------------------------------
#define T1P      0
#define P1S      49152
#define P1_A16   9216
#define P1_B     13312
#define P1_STAGE 37888
#define P3S      49152
#define P3_STAGE 24576
#define E_RF     99328
#define E_RF16   108544
#define E_RW     112640
#define E_SMEM   137216

__global__ __launch_bounds__(512)
void edge_kernel(const float* __restrict__ wgt,
                 const __half* __restrict__ B1,
                 const __half* __restrict__ B2,
                 const __half* __restrict__ RW,
                 const float* __restrict__ rbf,
                 const float* __restrict__ ib1, const float* __restrict__ ib2,
                 const float* __restrict__ rb,
                 const float* __restrict__ xh,
                 const int* __restrict__ ei, int E,
                 const float* __restrict__ vec, const float* __restrict__ ev,
                 float* __restrict__ dx, float* __restrict__ dvec)
{
    extern __shared__ char dsm[];
    const uint32_t S0 = smem_u32(dsm);
    float* m_st = (float*)dsm;                 // phase4 staging, stride 388
    const int tid  = threadIdx.x;
    const int wid  = tid >> 5;
    const int lane = tid & 31;
    const int row0 = blockIdx.x * 64;

    const int wm  = (wid >> 3) * 32;
    const int wn  = (wid & 7) * 48;
    const int gq  = lane >> 2;
    const int tig = lane & 3;
    const int a_r = (lane & 7) + ((lane & 8) ? 8 : 0);
    const int a_c = lane >> 4;
    const int b_r = (lane & 7) + ((lane & 16) ? 8 : 0);
    const int b_c = (lane >> 3) & 1;

    float acc[2][6][4];
#pragma unroll
    for (int i = 0; i < 2; i++)
#pragma unroll
        for (int j = 0; j < 6; j++)
#pragma unroll
            for (int k = 0; k < 4; k++) acc[i][j][k] = 0.0f;

    // ======================= phase 1: w1 = wgt @ iw1 =======================
    auto load_p1 = [&](int c) {
        const uint32_t S = S0 + P1S + (c & 1) * P1_STAGE;
        const int k0 = c * 32;
        {   // A fp32: 64 rows x 8 x 16B = 512 -> one per thread
            int r = tid >> 3, u = tid & 7;
            int gr = row0 + r; if (gr >= E) gr = E - 1;
            cp16(S + r * 144 + u * 16, wgt + (size_t)gr * 416 + k0 + u * 4);
        }
#pragma unroll
        for (int i = 0; i < 3; i++) {          // B1: 384 x 4 units = 1536
            int id = tid + i * 512;
            int r = id >> 2, u = id & 3;
            cp16(S + P1_B + SWZ64(r * 64 + u * 16),
                 B1 + (size_t)r * 416 + k0 + u * 8);
        }
        cp_commit();
    };

    load_p1(0);
    for (int c = 0; c < 13; c++) {
        const uint32_t S = S0 + P1S + (c & 1) * P1_STAGE;
        char* Sc = dsm + P1S + (c & 1) * P1_STAGE;

        cp_wait0();
        __syncthreads();                       // chunk c ready; prior mma done
        if (c + 1 < 13) load_p1(c + 1);

        // convert wgt fp32 -> fp16 plane (disjoint region -> no mid-sync)
        const int cr = tid >> 3, cg = tid & 7;
        float4 v = *(const float4*)(Sc + cr * 144 + cg * 16);
        {
            __half h0 = __float2half_rn(v.x), h1 = __float2half_rn(v.y);
            __half h2 = __float2half_rn(v.z), h3 = __float2half_rn(v.w);
            uint2 hp;
            hp.x = (uint32_t)__half_as_ushort(h0) | ((uint32_t)__half_as_ushort(h1) << 16);
            hp.y = (uint32_t)__half_as_ushort(h2) | ((uint32_t)__half_as_ushort(h3) << 16);
            *(uint2*)(Sc + P1_A16 + SWZ64(cr * 64 + cg * 8)) = hp;
        }
        __syncthreads();                       // plane visible before ldmatrix

        mma_chunk32(acc, S + P1_A16, S + P1_B, wm, wn, a_r, a_c, b_r, b_c);
    }
    __syncthreads();                           // p1 stage reads done

    // ============ phase 2: t1 = silu(w1+ib1) -> smem fp16 plane ============
#pragma unroll
    for (int mt = 0; mt < 2; mt++)
#pragma unroll
        for (int half = 0; half < 2; half++) {
            const int er = wm + mt * 16 + gq + half * 8;
#pragma unroll
            for (int nt = 0; nt < 6; nt++) {
                const int col = wn + nt * 8 + tig * 2;
                float s0 = silu_f(acc[mt][nt][half * 2 + 0] + ib1[col]);
                float s1 = silu_f(acc[mt][nt][half * 2 + 1] + ib1[col + 1]);
                __half h0 = __float2half_rn(s0);
                __half h1 = __float2half_rn(s1);
                const int ch = col >> 5, cc = col & 31;
                uint32_t off = ch * 4096 + SWZ64(er * 64 + cc * 2);
                *(uint32_t*)(dsm + T1P + off) =
                    (uint32_t)__half_as_ushort(h0) |
                    ((uint32_t)__half_as_ushort(h1) << 16);
            }
        }

    // ======================= phase 3: w2 = t1 @ iw2 ========================
#pragma unroll
    for (int i = 0; i < 2; i++)
#pragma unroll
        for (int j = 0; j < 6; j++)
#pragma unroll
            for (int k = 0; k < 4; k++) acc[i][j][k] = 0.0f;

    auto load_p3 = [&](int c) {
        const uint32_t S = S0 + P3S + (c & 1) * P3_STAGE;
        const int k0 = c * 32;
#pragma unroll
        for (int i = 0; i < 3; i++) {          // B2: 384 x 4 units = 1536
            int id = tid + i * 512;
            int r = id >> 2, u = id & 3;
            cp16(S + SWZ64(r * 64 + u * 16), B2 + (size_t)r * 384 + k0 + u * 8);
        }
        cp_commit();
    };

    load_p3(0);
    __syncthreads();                           // t1 plane visible to all
    for (int c = 0; c < 12; c++) {
        const uint32_t S = S0 + P3S + (c & 1) * P3_STAGE;
        cp_wait0();
        __syncthreads();                       // B chunk c ready; reuse fenced
        if (c + 1 < 12) load_p3(c + 1);
        mma_chunk32(acc, S0 + T1P + c * 4096, S, wm, wn, a_r, a_c, b_r, b_c);
    }
    __syncthreads();                           // t1 / stage reads done

    // ---- start rbf/rw loads (stage + t1 regions now reusable) ----
    {   // rbf fp32: 64 rows x 8 x 16B = 512
        int r = tid >> 3, u = tid & 7;
        int gr = row0 + r; if (gr >= E) gr = E - 1;
        cp16(S0 + E_RF + r * 144 + u * 16, rbf + (size_t)gr * 32 + u * 4);
    }
#pragma unroll
    for (int i = 0; i < 3; i++) {              // rw plane: 384 x 4 = 1536
        int id = tid + i * 512;
        int r = id >> 2, u = id & 3;
        cp16(S0 + E_RW + SWZ64(r * 64 + u * 16), RW + (size_t)r * 32 + u * 8);
    }
    cp_commit();

    // stage w2 + ib2 into m_st (aliases t1 plane + p3 stages)
#pragma unroll
    for (int mt = 0; mt < 2; mt++)
#pragma unroll
        for (int half = 0; half < 2; half++) {
            const int er = wm + mt * 16 + gq + half * 8;
#pragma unroll
            for (int nt = 0; nt < 6; nt++) {
                const int col = wn + nt * 8 + tig * 2;
                float2 o;
                o.x = acc[mt][nt][half * 2 + 0] + ib2[col];
                o.y = acc[mt][nt][half * 2 + 1] + ib2[col + 1];
                *(float2*)&m_st[er * 388 + col] = o;
            }
        }

    // ---- rbfh: rbf @ rw^T (single pass) ----
#pragma unroll
    for (int i = 0; i < 2; i++)
#pragma unroll
        for (int j = 0; j < 6; j++)
#pragma unroll
            for (int k = 0; k < 4; k++) acc[i][j][k] = 0.0f;

    cp_wait0(); __syncthreads();
    {   // convert rbf fp32 -> fp16 plane (disjoint region)
        const int cr = tid >> 3, cg = tid & 7;
        float4 v = *(const float4*)(dsm + E_RF + cr * 144 + cg * 16);
        __half h0 = __float2half_rn(v.x), h1 = __float2half_rn(v.y);
        __half h2 = __float2half_rn(v.z), h3 = __float2half_rn(v.w);
        uint2 hp;
        hp.x = (uint32_t)__half_as_ushort(h0) | ((uint32_t)__half_as_ushort(h1) << 16);
        hp.y = (uint32_t)__half_as_ushort(h2) | ((uint32_t)__half_as_ushort(h3) << 16);
        *(uint2*)(dsm + E_RF16 + SWZ64(cr * 64 + cg * 8)) = hp;
        __syncthreads();
    }
    mma_chunk32(acc, S0 + E_RF16, S0 + E_RW, wm, wn, a_r, a_c, b_r, b_c);

    // multiply own cells: m_st *= (rbfh + rb)
#pragma unroll
    for (int mt = 0; mt < 2; mt++)
#pragma unroll
        for (int half = 0; half < 2; half++) {
            const int er = wm + mt * 16 + gq + half * 8;
#pragma unroll
            for (int nt = 0; nt < 6; nt++) {
                const int col = wn + nt * 8 + tig * 2;
                float2 o = *(float2*)&m_st[er * 388 + col];
                o.x *= acc[mt][nt][half * 2 + 0] + rb[col];
                o.y *= acc[mt][nt][half * 2 + 1] + rb[col + 1];
                *(float2*)&m_st[er * 388 + col] = o;
            }
        }
    __syncthreads();

    // ==================== phase 4: warp-per-edge scatter ===================
    const float is3 = 0.57735026918962576f;   // 1/sqrt(3)
    const float ish = 0.08838834764831845f;   // 1/sqrt(128)
#pragma unroll
    for (int i = 0; i < 4; i++) {
        const int er = wid * 4 + i;
        const int e  = row0 + er;
        if (e >= E) continue;
        const int s = ei[e];
        const int d = ei[E + e];

        const float* st = m_st + er * 388;
        float4 a0 = *(const float4*)&st[lane * 4];
        float4 a1 = *(const float4*)&st[128 + lane * 4];
        float4 a2 = *(const float4*)&st[256 + lane * 4];

        const float* xr = xh + (size_t)s * 384;
        float4 x0 = *(const float4*)&xr[lane * 4];
        float4 x1 = *(const float4*)&xr[128 + lane * 4];
        float4 x2 = *(const float4*)&xr[256 + lane * 4];

        float4 xm, h2, h3;
        xm.x = a0.x * x0.x;  xm.y = a0.y * x0.y;
        xm.z = a0.z * x0.z;  xm.w = a0.w * x0.w;
        h2.x = a1.x * x1.x * is3;  h2.y = a1.y * x1.y * is3;
        h2.z = a1.z * x1.z * is3;  h2.w = a1.w * x1.w * is3;
        h3.x = a2.x * x2.x;  h3.y = a2.y * x2.y;
        h3.z = a2.z * x2.z;  h3.w = a2.w * x2.w;

        red_add_v4(dx + (size_t)d * 128 + lane * 4, xm);

        float evd[3];
        evd[0] = __ldg(&ev[(size_t)e * 3 + 0]);
        evd[1] = __ldg(&ev[(size_t)e * 3 + 1]);
        evd[2] = __ldg(&ev[(size_t)e * 3 + 2]);
        const float4* v4 = (const float4*)(vec + (size_t)s * 384);
#pragma unroll
        for (int t = 0; t < 3; t++) {
            float4 v = v4[t * 32 + lane];
            float4 o;
            o.x = (v.x * h2.x + h3.x * evd[t]) * ish;
            o.y = (v.y * h2.y + h3.y * evd[t]) * ish;
            o.z = (v.z * h2.z + h3.z * evd[t]) * ish;
            o.w = (v.w * h2.w + h3.w * evd[t]) * ish;
            red_add_v4(dvec + ((size_t)d * 3 + t) * 128 + lane * 4, o);
        }
    }
}

// ---------------------------------------------------------------------------
// Transpose weights: src [K,N] fp32 -> single fp16 plane [N,K]
// ---------------------------------------------------------------------------
__global__ void splitT(const float* __restrict__ src,
                       __half* __restrict__ h16,
                       int K, int N)
{
    int t = blockIdx.x * blockDim.x + threadIdx.x;
    if (t >= N * K) return;
    int n = t / K, k = t - n * K;
    h16[t] = __float2half_rn(src[(size_t)k * N + n]);
}

// ---------------------------------------------------------------------------
// FFMA2 SGEMM for the node GEMMs
// ---------------------------------------------------------------------------
#define BM 128
#define BN 128
#define BK 16

__device__ __forceinline__ unsigned long long pack2(float lo, float hi) {
    unsigned long long r;
    asm("mov.b64 %0, {%1, %2};" : "=l"(r) : "f"(lo), "f"(hi));
    return r;
}
__device__ __forceinline__ void unpack2(unsigned long long v, float& lo, float& hi) {
    asm("mov.b64 {%0, %1}, %2;" : "=f"(lo), "=f"(hi) : "l"(v));
}
__device__ __forceinline__ void ffma2(unsigned long long& d,
                                      unsigned long long a, unsigned long long b) {
    asm("fma.rn.f32x2 %0, %1, %2, %0;" : "+l"(d) : "l"(a), "l"(b));
}

template<bool SILU>
__global__ __launch_bounds__(256, 2)
void sgemm_bias_act(const float* __restrict__ A, const float* __restrict__ B,
                    const float* __restrict__ bias, float* __restrict__ C,
                    int M, int N, int K)
{
    __shared__ float As[BK][BM + 4];
    __shared__ float Bs[BK][BN];

    const int tid  = threadIdx.x;
    const int tx   = tid & 15;
    const int ty   = tid >> 4;
    const int row0 = blockIdx.y * BM;
    const int col0 = blockIdx.x * BN;

    unsigned long long acc2[8][4];
#pragma unroll
    for (int i = 0; i < 8; i++)
#pragma unroll
        for (int j = 0; j < 4; j++) acc2[i][j] = 0ull;

    const int a_row = tid >> 2;
    const int a_seg = tid & 3;
    const int b_kk  = tid >> 5;
    const int b_c4  = (tid & 31) << 2;

    for (int k0 = 0; k0 < K; k0 += BK) {
#pragma unroll
        for (int it = 0; it < 2; it++) {
            int r  = a_row + it * 64;
            int gr = row0 + r;
            float4 v = make_float4(0.f, 0.f, 0.f, 0.f);
            if (gr < M)
                v = *(const float4*)&A[(size_t)gr * K + k0 + a_seg * 4];
            As[a_seg * 4 + 0][r] = v.x;
            As[a_seg * 4 + 1][r] = v.y;
            As[a_seg * 4 + 2][r] = v.z;
            As[a_seg * 4 + 3][r] = v.w;
        }
#pragma unroll
        for (int it = 0; it < 2; it++) {
            int kk = b_kk + it * 8;
            *(float4*)&Bs[kk][b_c4] =
                *(const float4*)&B[(size_t)(k0 + kk) * N + col0 + b_c4];
        }
        __syncthreads();

#pragma unroll
        for (int kk = 0; kk < BK; kk++) {
            float4 a0 = *(const float4*)&As[kk][ty * 4];
            float4 a1 = *(const float4*)&As[kk][64 + ty * 4];
            float4 b0 = *(const float4*)&Bs[kk][tx * 4];
            float4 b1 = *(const float4*)&Bs[kk][64 + tx * 4];
            unsigned long long bp[4] = {
                pack2(b0.x, b0.y), pack2(b0.z, b0.w),
                pack2(b1.x, b1.y), pack2(b1.z, b1.w)
            };
            float av[8] = {a0.x, a0.y, a0.z, a0.w, a1.x, a1.y, a1.z, a1.w};
#pragma unroll
            for (int i = 0; i < 8; i++) {
                unsigned long long ap = pack2(av[i], av[i]);
#pragma unroll
                for (int jp = 0; jp < 4; jp++)
                    ffma2(acc2[i][jp], ap, bp[jp]);
            }
        }
        __syncthreads();
    }

#pragma unroll
    for (int i = 0; i < 8; i++) {
        int r  = (i < 4) ? (ty * 4 + i) : (64 + ty * 4 + (i - 4));
        int gr = row0 + r;
        if (gr >= M) continue;
#pragma unroll
        for (int jg = 0; jg < 2; jg++) {
            int c  = (jg == 0) ? (tx * 4) : (64 + tx * 4);
            int gc = col0 + c;
            float4 bi = *(const float4*)&bias[gc];
            float4 o;
            unpack2(acc2[i][jg * 2 + 0], o.x, o.y);
            unpack2(acc2[i][jg * 2 + 1], o.z, o.w);
            o.x += bi.x; o.y += bi.y; o.z += bi.z; o.w += bi.w;
            if (SILU) {
                o.x = silu_f(o.x); o.y = silu_f(o.y);
                o.z = silu_f(o.z); o.w = silu_f(o.w);
            }
            *(float4*)&C[(size_t)gr * N + gc] = o;
        }
    }
}

// ---------------------------------------------------------------------------
// Launch
// ---------------------------------------------------------------------------
extern "C" void kernel_launch(void* const* d_in, const int* in_sizes, int n_in,
                              void* d_out, int out_size)
{
    const float* x    = (const float*)d_in[0];
    const float* vec  = (const float*)d_in[1];
    const int*   ei   = (const int*)  d_in[2];
    const float* rbf  = (const float*)d_in[3];
    const float* wgt  = (const float*)d_in[4];
    const float* ev   = (const float*)d_in[5];
    const float* xw1  = (const float*)d_in[6];
    const float* xb1  = (const float*)d_in[7];
    const float* xw2  = (const float*)d_in[8];
    const float* xb2  = (const float*)d_in[9];
    const float* rw   = (const float*)d_in[10];
    const float* rb   = (const float*)d_in[11];
    const float* iw1  = (const float*)d_in[12];
    const float* ib1  = (const float*)d_in[13];
    const float* iw2  = (const float*)d_in[14];
    const float* ib2  = (const float*)d_in[15];

    const int nn = in_sizes[0] / 128;
    const int ne = in_sizes[2] / 2;

    float* out  = (float*)d_out;
    float* dx   = out;
    float* dvec = out + (size_t)nn * 128;

    float *p_h1, *p_xh;
    __half *p_b1, *p_b2, *p_rw;
    cudaGetSymbolAddress((void**)&p_h1, g_h1);
    cudaGetSymbolAddress((void**)&p_xh, g_xh);
    cudaGetSymbolAddress((void**)&p_b1, g_b1);
    cudaGetSymbolAddress((void**)&p_b2, g_b2);
    cudaGetSymbolAddress((void**)&p_rw, g_rw);

    cudaFuncSetAttribute(edge_kernel,
                         cudaFuncAttributeMaxDynamicSharedMemorySize, E_SMEM);

    cudaMemsetAsync(d_out, 0, (size_t)out_size * sizeof(float));

    dim3 blk(256);

    // weight conversions (tiny)
    splitT<<<(384 * 416 + 255) / 256, blk>>>(iw1, p_b1, 416, 384);
    splitT<<<(384 * 384 + 255) / 256, blk>>>(iw2, p_b2, 384, 384);
    splitT<<<(384 * 32  + 255) / 256, blk>>>(rw,  p_rw, 32,  384);

    // node projection (FFMA2): xh = silu(x@xw1+xb1)@xw2+xb2
    sgemm_bias_act<true ><<<dim3(1, (nn + BM - 1) / BM), blk>>>(x,    xw1, xb1, p_h1, nn, 128, 128);
    sgemm_bias_act<false><<<dim3(3, (nn + BM - 1) / BM), blk>>>(p_h1, xw2, xb2, p_xh, nn, 384, 128);

    // fused edge pipeline
    const int mtiles = (ne + 63) / 64;
    edge_kernel<<<mtiles, 512, E_SMEM>>>(wgt, p_b1, p_b2, p_rw, rbf,
                                         ib1, ib2, rb, p_xh, ei, ne,
                                         vec, ev, dx, dvec);
}